// round 11
// baseline (speedup 1.0000x reference)
#include <cuda_runtime.h>
#include <cstdint>

// Problem constants
#define NB   8
#define LSEQ 1024
#define EMB  1024
#define NH   16
#define HD   64

// Scratch (allocation-free rule: device globals)
__device__ float g_Qp[NB * LSEQ * EMB];
__device__ float g_Kp[NB * LSEQ * EMB];
__device__ float g_Vp[NB * LSEQ * EMB];
__device__ float g_AO[NB * LSEQ * EMB];
__device__ float g_Wt[EMB * EMB];       // tf32-canonical Wo

// ---------------------------------------------------------------------------
__device__ __forceinline__ uint32_t tf32r(float f) {
    uint32_t u;
    asm("cvt.rna.tf32.f32 %0, %1;" : "=r"(u) : "f"(f));
    return u;
}
__device__ __forceinline__ float ex2a(float x) {
    float y;
    asm("ex2.approx.f32 %0, %1;" : "=f"(y) : "f"(x));
    return y;
}
__device__ __forceinline__ uint32_t smem_u32(const void* p) {
    uint32_t a;
    asm("{ .reg .u64 t; cvta.to.shared.u64 t, %1; cvt.u32.u64 %0, t; }"
        : "=r"(a) : "l"(p));
    return a;
}
__device__ __forceinline__ void cp16(uint32_t s, const float* g) {
    asm volatile("cp.async.cg.shared.global [%0], [%1], 16;" :: "r"(s), "l"(g));
}
#define CP_COMMIT() asm volatile("cp.async.commit_group;" ::: "memory")
#define CP_WAIT(n)  asm volatile("cp.async.wait_group %0;" :: "n"(n) : "memory")

// D += A*B, m16n8k8 tf32. NOT volatile: pure arithmetic, let ptxas schedule.
__device__ __forceinline__ void mma8(float* d, const uint32_t* a, const uint32_t* b) {
    asm("mma.sync.aligned.m16n8k8.row.col.f32.tf32.tf32.f32 "
        "{%0,%1,%2,%3}, {%4,%5,%6,%7}, {%8,%9}, {%0,%1,%2,%3};"
        : "+f"(d[0]), "+f"(d[1]), "+f"(d[2]), "+f"(d[3])
        : "r"(a[0]), "r"(a[1]), "r"(a[2]), "r"(a[3]), "r"(b[0]), "r"(b[1]));
}

// C-frag (16x8 f32) -> A-frag (tf32) via shuffles
__device__ __forceinline__ void c2a(const float* p, uint32_t* a, int lane) {
    const unsigned FM = 0xffffffffu;
    int s0 = (lane & ~3) | ((lane & 3) >> 1);
    int s2 = s0 + 2;
    bool odd = lane & 1;
    float v00 = __shfl_sync(FM, p[0], s0), v01 = __shfl_sync(FM, p[1], s0);
    float v20 = __shfl_sync(FM, p[2], s0), v21 = __shfl_sync(FM, p[3], s0);
    float w00 = __shfl_sync(FM, p[0], s2), w01 = __shfl_sync(FM, p[1], s2);
    float w20 = __shfl_sync(FM, p[2], s2), w21 = __shfl_sync(FM, p[3], s2);
    a[0] = tf32r(odd ? v01 : v00);
    a[1] = tf32r(odd ? v21 : v20);
    a[2] = tf32r(odd ? w01 : w00);
    a[3] = tf32r(odd ? w21 : w20);
}

// ===========================================================================
// Fused front-end: blockIdx.y in {0,1,2} -> Q/K/V projection (128-row tile),
// blockIdx.y == 3 -> canonicalize Wo into g_Wt.
// Projection: C[128 x 64] = A[128 x 64] * W[64 x 64]^T, tf32-canonical out.
// ===========================================================================
__global__ __launch_bounds__(256) void proj_all(
    const float* __restrict__ q, const float* __restrict__ k,
    const float* __restrict__ v,
    const float* __restrict__ Wq, const float* __restrict__ Wk,
    const float* __restrict__ Wv,
    float* __restrict__ Qp, float* __restrict__ Kp, float* __restrict__ Vp,
    const float* __restrict__ Wo, float* __restrict__ Wt)
{
    const int t = threadIdx.x;
    if (blockIdx.y == 3) {
        int i = blockIdx.x * 256 + t;
        float4 w = reinterpret_cast<const float4*>(Wo)[i];
        uint4 u = make_uint4(tf32r(w.x), tf32r(w.y), tf32r(w.z), tf32r(w.w));
        reinterpret_cast<uint4*>(Wt)[i] = u;
        return;
    }

    extern __shared__ uint32_t sm[];
    uint32_t* As = sm;            // 128*68
    uint32_t* Bs = sm + 128 * 68; // 64*68

    const float* A = (blockIdx.y == 0) ? q : (blockIdx.y == 1) ? k : v;
    const float* B = (blockIdx.y == 0) ? Wq : (blockIdx.y == 1) ? Wk : Wv;
    float* C = (blockIdx.y == 0) ? Qp : (blockIdx.y == 1) ? Kp : Vp;

    const int lane = t & 31, wid = t >> 5;
    const int wm = wid & 1, wn = wid >> 1;
    const int g = lane >> 2, tg = lane & 3;

    A += (long long)blockIdx.x * 128 * 64;
    C += (long long)blockIdx.x * 128 * 64;

#pragma unroll
    for (int i = 0; i < 8; ++i) {
        int s = t + i * 256, r = s >> 4, c4 = (s & 15) << 2;
        float4 vv = *reinterpret_cast<const float4*>(A + (long long)r * 64 + c4);
        uint4 u = make_uint4(tf32r(vv.x), tf32r(vv.y), tf32r(vv.z), tf32r(vv.w));
        *reinterpret_cast<uint4*>(&As[r * 68 + c4]) = u;   // row pad 272B, 16B aligned
    }
#pragma unroll
    for (int i = 0; i < 4; ++i) {
        int s = t + i * 256, r = s >> 4, c4 = (s & 15) << 2;
        float4 vv = *reinterpret_cast<const float4*>(B + (long long)r * 64 + c4);
        uint4 u = make_uint4(tf32r(vv.x), tf32r(vv.y), tf32r(vv.z), tf32r(vv.w));
        *reinterpret_cast<uint4*>(&Bs[r * 68 + c4]) = u;
    }
    __syncthreads();

    float acc[4][2][4];
#pragma unroll
    for (int i = 0; i < 4; ++i)
#pragma unroll
        for (int j = 0; j < 2; ++j)
#pragma unroll
            for (int e = 0; e < 4; ++e) acc[i][j][e] = 0.f;

#pragma unroll
    for (int ks = 0; ks < 8; ++ks) {
        int kb = ks * 8;
        uint32_t af[4][4];
#pragma unroll
        for (int mt = 0; mt < 4; ++mt) {
            int row = wm * 64 + mt * 16 + g;
            af[mt][0] = As[row * 68 + kb + tg];
            af[mt][1] = As[(row + 8) * 68 + kb + tg];
            af[mt][2] = As[row * 68 + kb + tg + 4];
            af[mt][3] = As[(row + 8) * 68 + kb + tg + 4];
        }
        uint32_t bf[2][2];
#pragma unroll
        for (int nt = 0; nt < 2; ++nt) {
            int col = wn * 16 + nt * 8 + g;
            bf[nt][0] = Bs[col * 68 + kb + tg];
            bf[nt][1] = Bs[col * 68 + kb + tg + 4];
        }
#pragma unroll
        for (int mt = 0; mt < 4; ++mt)
#pragma unroll
            for (int nt = 0; nt < 2; ++nt)
                mma8(acc[mt][nt], af[mt], bf[nt]);
    }

#pragma unroll
    for (int mt = 0; mt < 4; ++mt) {
        int row = wm * 64 + mt * 16 + g;
#pragma unroll
        for (int nt = 0; nt < 2; ++nt) {
            int col = wn * 16 + nt * 8 + 2 * tg;
            uint2 o0 = make_uint2(tf32r(acc[mt][nt][0]), tf32r(acc[mt][nt][1]));
            uint2 o1 = make_uint2(tf32r(acc[mt][nt][2]), tf32r(acc[mt][nt][3]));
            *reinterpret_cast<uint2*>(C + (long long)row * 64 + col) = o0;
            *reinterpret_cast<uint2*>(C + (long long)(row + 8) * 64 + col) = o1;
        }
    }
}

// ===========================================================================
// Big GEMM: C[8192 x 1024] = A[8192 x 1024] * B[1024 x 1024]^T.
// A,B tf32-canonical. 128x128 tile, K chunked 32, cp.async double buffer.
// 72 KB smem + <=128 regs -> 2 CTAs/SM.
// ===========================================================================
__global__ __launch_bounds__(256, 2) void gemm_big(
    const float* __restrict__ A, const float* __restrict__ B,
    float* __restrict__ C)
{
    extern __shared__ uint32_t sm[];
    const uint32_t sbase = smem_u32(sm);

    const int t = threadIdx.x, lane = t & 31, wid = t >> 5;
    const int wm = wid & 1, wn = wid >> 1;
    const int g = lane >> 2, tg = lane & 3;

    A += (long long)blockIdx.x * 128 * 1024;
    B += (long long)blockIdx.y * 128 * 1024;
    C += (long long)blockIdx.x * 128 * 1024 + (long long)blockIdx.y * 128;

    float acc[4][4][4];
#pragma unroll
    for (int i = 0; i < 4; ++i)
#pragma unroll
        for (int j = 0; j < 4; ++j)
#pragma unroll
            for (int e = 0; e < 4; ++e) acc[i][j][e] = 0.f;

#pragma unroll
    for (int i = 0; i < 4; ++i) {
        int s = t + i * 256, r = s >> 3, c4 = (s & 7) << 2;
        cp16(sbase + (r * 36 + c4) * 4, A + (long long)r * 1024 + c4);
        cp16(sbase + (9216 + r * 36 + c4) * 4, B + (long long)r * 1024 + c4);
    }
    CP_COMMIT();

    for (int ck = 0; ck < 32; ++ck) {
        __syncthreads();
        if (ck < 31) {
            int kc = (ck + 1) * 32, b = (ck + 1) & 1;
#pragma unroll
            for (int i = 0; i < 4; ++i) {
                int s = t + i * 256, r = s >> 3, c4 = (s & 7) << 2;
                cp16(sbase + (b * 4608 + r * 36 + c4) * 4,
                     A + (long long)r * 1024 + kc + c4);
                cp16(sbase + (9216 + b * 4608 + r * 36 + c4) * 4,
                     B + (long long)r * 1024 + kc + c4);
            }
            CP_COMMIT();
            CP_WAIT(1);
        } else {
            CP_WAIT(0);
        }
        __syncthreads();

        const uint32_t* As = sm + (ck & 1) * 4608;
        const uint32_t* Bs = sm + 9216 + (ck & 1) * 4608;
#pragma unroll
        for (int ks = 0; ks < 4; ++ks) {
            int kb = ks * 8;
            uint32_t af[4][4];
#pragma unroll
            for (int mt = 0; mt < 4; ++mt) {
                int row = wm * 64 + mt * 16 + g;
                af[mt][0] = As[row * 36 + kb + tg];
                af[mt][1] = As[(row + 8) * 36 + kb + tg];
                af[mt][2] = As[row * 36 + kb + tg + 4];
                af[mt][3] = As[(row + 8) * 36 + kb + tg + 4];
            }
            uint32_t bf[4][2];
#pragma unroll
            for (int nt = 0; nt < 4; ++nt) {
                int col = wn * 32 + nt * 8 + g;
                bf[nt][0] = Bs[col * 36 + kb + tg];
                bf[nt][1] = Bs[col * 36 + kb + tg + 4];
            }
#pragma unroll
            for (int mt = 0; mt < 4; ++mt)
#pragma unroll
                for (int nt = 0; nt < 4; ++nt)
                    mma8(acc[mt][nt], af[mt], bf[nt]);
        }
    }

#pragma unroll
    for (int mt = 0; mt < 4; ++mt) {
        int row = wm * 64 + mt * 16 + g;
#pragma unroll
        for (int nt = 0; nt < 4; ++nt) {
            int col = wn * 32 + nt * 8 + 2 * tg;
            *reinterpret_cast<float2*>(C + (long long)row * 1024 + col) =
                make_float2(acc[mt][nt][0], acc[mt][nt][1]);
            *reinterpret_cast<float2*>(C + (long long)(row + 8) * 1024 + col) =
                make_float2(acc[mt][nt][2], acc[mt][nt][3]);
        }
    }
}

// ===========================================================================
// Flash attention, tf32 mma.sync, BK=64 double-buffered, 2 CTAs/SM.
// 8 warps x 16 q-rows each (no k-split, no cross-warp O combine).
// smem words: Qs 0 (128*68), Ks0 8704, Ks1 13056 (64*68 each),
//             Vs0 17408, Vs1 22016 (64*72 each). Total 26624 w = 104 KB.
// ===========================================================================
__global__ __launch_bounds__(256, 2) void attn_tc(
    const float* __restrict__ Qp, const float* __restrict__ Kp,
    const float* __restrict__ Vp, float* __restrict__ AO)
{
    extern __shared__ uint32_t sm[];
    const uint32_t sbase = smem_u32(sm);

    const int t = threadIdx.x, lane = t & 31, wid = t >> 5;
    const int g = lane >> 2, tg = lane & 3;
    const int qt = blockIdx.x, h = blockIdx.y, n = blockIdx.z;

    const long long base = ((long long)n << 20) + h * 64;
    const float* Qb = Qp + base + (long long)(qt * 128) * 1024;

    // prefetch Q [128x64] + K/V tile 0 [64x64]
#pragma unroll
    for (int i = 0; i < 8; ++i) {
        int s = t + i * 256, r = s >> 4, c4 = (s & 15) << 2;
        cp16(sbase + (r * 68 + c4) * 4, Qb + (long long)r * 1024 + c4);
    }
#pragma unroll
    for (int i = 0; i < 4; ++i) {
        int s = t + i * 256, r = s >> 4, c4 = (s & 15) << 2;
        cp16(sbase + (8704 + r * 68 + c4) * 4, Kp + base + (long long)r * 1024 + c4);
        cp16(sbase + (17408 + r * 72 + c4) * 4, Vp + base + (long long)r * 1024 + c4);
    }
    CP_COMMIT();

    float Of[8][4];
    float lsum[2] = {0.f, 0.f};
#pragma unroll
    for (int dtl = 0; dtl < 8; ++dtl)
#pragma unroll
        for (int e = 0; e < 4; ++e) Of[dtl][e] = 0.f;

    const float CS = 0.03125f * 1.44269504088896f;   // 1/sqrt(1024) * log2(e)
    const int qrow = wid * 16 + g;                   // this thread's base q row

    for (int kt = 0; kt < 16; ++kt) {
        __syncthreads();
        if (kt < 15) {
            int b = (kt + 1) & 1;
            const float* Kb = Kp + base + (long long)((kt + 1) * 64) * 1024;
            const float* Vb = Vp + base + (long long)((kt + 1) * 64) * 1024;
#pragma unroll
            for (int i = 0; i < 4; ++i) {
                int s = t + i * 256, r = s >> 4, c4 = (s & 15) << 2;
                cp16(sbase + (8704 + b * 4352 + r * 68 + c4) * 4,
                     Kb + (long long)r * 1024 + c4);
                cp16(sbase + (17408 + b * 4608 + r * 72 + c4) * 4,
                     Vb + (long long)r * 1024 + c4);
            }
            CP_COMMIT();
            CP_WAIT(1);
        } else {
            CP_WAIT(0);
        }
        __syncthreads();

        const uint32_t* Qs = sm;
        const uint32_t* Ks = sm + 8704 + (kt & 1) * 4352;
        const uint32_t* Vs = sm + 17408 + (kt & 1) * 4608;

        // ---- S = Q K^T : warp tile 16q x 64k ----
        float Sf[8][4];
#pragma unroll
        for (int nt = 0; nt < 8; ++nt)
#pragma unroll
            for (int e = 0; e < 4; ++e) Sf[nt][e] = 0.f;

#pragma unroll
        for (int ds = 0; ds < 8; ++ds) {
            int kb = ds * 8;
            uint32_t af[4];
            af[0] = Qs[qrow * 68 + kb + tg];
            af[1] = Qs[(qrow + 8) * 68 + kb + tg];
            af[2] = Qs[qrow * 68 + kb + tg + 4];
            af[3] = Qs[(qrow + 8) * 68 + kb + tg + 4];
#pragma unroll
            for (int nt = 0; nt < 8; ++nt) {
                int kr = nt * 8 + g;
                uint32_t bf[2];
                bf[0] = Ks[kr * 68 + kb + tg];
                bf[1] = Ks[kr * 68 + kb + tg + 4];
                mma8(Sf[nt], af, bf);
            }
        }

        // ---- exp(slice 0), then interleave c2a(ks) | exp(ks+1) | PV(ks) ----
        {
            float e0 = ex2a(Sf[0][0] * CS), e1 = ex2a(Sf[0][1] * CS);
            float e2 = ex2a(Sf[0][2] * CS), e3 = ex2a(Sf[0][3] * CS);
            Sf[0][0] = e0; Sf[0][1] = e1; Sf[0][2] = e2; Sf[0][3] = e3;
            lsum[0] += e0 + e1; lsum[1] += e2 + e3;
        }
#pragma unroll
        for (int ks = 0; ks < 8; ++ks) {
            uint32_t pa[4];
            c2a(Sf[ks], pa, lane);
            if (ks < 7) {
                float e0 = ex2a(Sf[ks + 1][0] * CS), e1 = ex2a(Sf[ks + 1][1] * CS);
                float e2 = ex2a(Sf[ks + 1][2] * CS), e3 = ex2a(Sf[ks + 1][3] * CS);
                Sf[ks + 1][0] = e0; Sf[ks + 1][1] = e1;
                Sf[ks + 1][2] = e2; Sf[ks + 1][3] = e3;
                lsum[0] += e0 + e1; lsum[1] += e2 + e3;
            }
            int kr = ks * 8;
#pragma unroll
            for (int dtl = 0; dtl < 8; ++dtl) {
                uint32_t bf[2];
                bf[0] = Vs[(kr + tg) * 72 + dtl * 8 + g];
                bf[1] = Vs[(kr + tg + 4) * 72 + dtl * 8 + g];
                mma8(Of[dtl], pa, bf);
            }
        }
    }

    // ---- epilogue: quad-reduce l, normalize, write (warp-private rows) ----
    const unsigned FM = 0xffffffffu;
#pragma unroll
    for (int hh = 0; hh < 2; ++hh) {
        float v = lsum[hh];
        v += __shfl_xor_sync(FM, v, 1);
        v += __shfl_xor_sync(FM, v, 2);
        lsum[hh] = v;
    }
    float inv0 = 1.f / lsum[0], inv1 = 1.f / lsum[1];

    const int q0 = qt * 128 + qrow;
    float* Ob0 = AO + ((long long)n * 1024 + q0) * 1024 + h * 64;
    float* Ob1 = AO + ((long long)n * 1024 + q0 + 8) * 1024 + h * 64;
#pragma unroll
    for (int dtl = 0; dtl < 8; ++dtl) {
        int d = dtl * 8 + 2 * tg;
        uint2 o0 = make_uint2(tf32r(Of[dtl][0] * inv0), tf32r(Of[dtl][1] * inv0));
        uint2 o1 = make_uint2(tf32r(Of[dtl][2] * inv1), tf32r(Of[dtl][3] * inv1));
        *reinterpret_cast<uint2*>(Ob0 + d) = o0;
        *reinterpret_cast<uint2*>(Ob1 + d) = o1;
    }
}

// ===========================================================================
extern "C" void kernel_launch(void* const* d_in, const int* in_sizes, int n_in,
                              void* d_out, int out_size)
{
    (void)in_sizes; (void)n_in; (void)out_size;
    const float* key   = (const float*)d_in[0];
    const float* query = (const float*)d_in[1];
    const float* value = (const float*)d_in[2];
    /* d_in[3] = mask — faithfully ignored (reference no-op) */
    const float* Wq = (const float*)d_in[4];
    const float* Wk = (const float*)d_in[5];
    const float* Wv = (const float*)d_in[6];
    const float* Wo = (const float*)d_in[7];
    float* out = (float*)d_out;

    float *Qp, *Kp, *Vp, *AO, *Wt;
    cudaGetSymbolAddress((void**)&Qp, g_Qp);
    cudaGetSymbolAddress((void**)&Kp, g_Kp);
    cudaGetSymbolAddress((void**)&Vp, g_Vp);
    cudaGetSymbolAddress((void**)&AO, g_AO);
    cudaGetSymbolAddress((void**)&Wt, g_Wt);

    const int smem_proj = (128 * 68 + 64 * 68) * 4;            // 52224
    const int smem_big  = 18432 * 4;                           // 73728
    const int smem_attn = 26624 * 4;                           // 106496
    cudaFuncSetAttribute(proj_all,
        cudaFuncAttributeMaxDynamicSharedMemorySize, smem_proj);
    cudaFuncSetAttribute(gemm_big,
        cudaFuncAttributeMaxDynamicSharedMemorySize, smem_big);
    cudaFuncSetAttribute(attn_tc,
        cudaFuncAttributeMaxDynamicSharedMemorySize, smem_attn);

    dim3 blk(256);

    // Fused projections (y=0..2) + Wo canonicalization (y=3)
    proj_all<<<dim3(1024, 4), blk, smem_proj>>>(
        query, key, value, Wq, Wk, Wv, Qp, Kp, Vp, Wo, Wt);

    // Attention: grid (q-tiles=8, heads=16, batch=8)
    attn_tc<<<dim3(8, NH, NB), blk, smem_attn>>>(Qp, Kp, Vp, AO);

    // Output projection: out = AO * Wt^T
    gemm_big<<<dim3(64, 8), blk, smem_big>>>(AO, Wt, out);
}

// round 12
// speedup vs baseline: 1.9444x; 1.9444x over previous
#include <cuda_runtime.h>
#include <cuda_fp16.h>
#include <cstdint>

// Problem constants
#define NB   8
#define LSEQ 1024
#define EMB  1024
#define NH   16
#define HD   64

// Scratch (allocation-free rule: device globals) — fp16 intermediates
__device__ __half g_Qp[NB * LSEQ * EMB];
__device__ __half g_Kp[NB * LSEQ * EMB];
__device__ __half g_Vt[NB * LSEQ * EMB];   // V packed: [(n,h)][l/2][d] half2 (pairs along l)
__device__ __half g_AO[NB * LSEQ * EMB];
__device__ __half g_Wt[EMB * EMB];          // fp16 Wo

// ---------------------------------------------------------------------------
__device__ __forceinline__ uint32_t pack2(float lo, float hi) {
    __half2 h = __floats2half2_rn(lo, hi);
    return *reinterpret_cast<uint32_t*>(&h);
}
__device__ __forceinline__ float ex2a(float x) {
    float y;
    asm("ex2.approx.f32 %0, %1;" : "=f"(y) : "f"(x));
    return y;
}
__device__ __forceinline__ uint32_t smem_u32(const void* p) {
    uint32_t a;
    asm("{ .reg .u64 t; cvta.to.shared.u64 t, %1; cvt.u32.u64 %0, t; }"
        : "=r"(a) : "l"(p));
    return a;
}
__device__ __forceinline__ void cp16(uint32_t s, const void* g) {
    asm volatile("cp.async.cg.shared.global [%0], [%1], 16;" :: "r"(s), "l"(g));
}
#define CP_COMMIT() asm volatile("cp.async.commit_group;" ::: "memory")
#define CP_WAIT(n)  asm volatile("cp.async.wait_group %0;" :: "n"(n) : "memory")

// D += A*B, m16n8k16 fp16 inputs, fp32 accum.
__device__ __forceinline__ void mma16(float* d, const uint32_t* a, const uint32_t* b) {
    asm("mma.sync.aligned.m16n8k16.row.col.f32.f16.f16.f32 "
        "{%0,%1,%2,%3}, {%4,%5,%6,%7}, {%8,%9}, {%0,%1,%2,%3};"
        : "+f"(d[0]), "+f"(d[1]), "+f"(d[2]), "+f"(d[3])
        : "r"(a[0]), "r"(a[1]), "r"(a[2]), "r"(a[3]), "r"(b[0]), "r"(b[1]));
}

// ===========================================================================
// Fused front-end. blockIdx.y: 0=Q proj, 1=K proj, 2=V proj (packed), 3=Wo->fp16.
// Proj: C[128 x 64] = X[128 x 64] * W[64 x 64]^T, fp32 in, fp16 out.
// smem (words): As 128*36, Bs 64*36.
// ===========================================================================
__global__ __launch_bounds__(256) void proj_all(
    const float* __restrict__ q, const float* __restrict__ k,
    const float* __restrict__ v,
    const float* __restrict__ Wq, const float* __restrict__ Wk,
    const float* __restrict__ Wv,
    __half* __restrict__ Qp, __half* __restrict__ Kp, __half* __restrict__ Vt,
    const float* __restrict__ Wo, __half* __restrict__ Wt)
{
    const int t = threadIdx.x;
    if (blockIdx.y == 3) {
        int i = blockIdx.x * 256 + t;
        float4 w = reinterpret_cast<const float4*>(Wo)[i];
        uint2 u = make_uint2(pack2(w.x, w.y), pack2(w.z, w.w));
        *reinterpret_cast<uint2*>(reinterpret_cast<uint32_t*>(Wt) + i * 2) = u;
        return;
    }

    extern __shared__ uint32_t sm[];
    uint32_t* As = sm;            // [128][36] words (32 data = 64 halves + pad)
    uint32_t* Bs = sm + 128 * 36;

    const float* A = (blockIdx.y == 0) ? q : (blockIdx.y == 1) ? k : v;
    const float* B = (blockIdx.y == 0) ? Wq : (blockIdx.y == 1) ? Wk : Wv;

    const int lane = t & 31, wid = t >> 5;
    const int wm = wid & 1, wn = wid >> 1;
    const int g = lane >> 2, tg = lane & 3;

    A += (long long)blockIdx.x * 128 * 64;

    // stage X [128x64] fp32 -> fp16 pairs (contiguous along d)
#pragma unroll
    for (int i = 0; i < 8; ++i) {
        int s = t + i * 256, r = s >> 4, c4 = (s & 15) << 2;
        float4 vv = *reinterpret_cast<const float4*>(A + (long long)r * 64 + c4);
        uint2 u = make_uint2(pack2(vv.x, vv.y), pack2(vv.z, vv.w));
        *reinterpret_cast<uint2*>(&As[r * 36 + (c4 >> 1)]) = u;
    }
#pragma unroll
    for (int i = 0; i < 4; ++i) {
        int s = t + i * 256, r = s >> 4, c4 = (s & 15) << 2;
        float4 vv = *reinterpret_cast<const float4*>(B + (long long)r * 64 + c4);
        uint2 u = make_uint2(pack2(vv.x, vv.y), pack2(vv.z, vv.w));
        *reinterpret_cast<uint2*>(&Bs[r * 36 + (c4 >> 1)]) = u;
    }
    __syncthreads();

    float acc[4][2][4];
#pragma unroll
    for (int i = 0; i < 4; ++i)
#pragma unroll
        for (int j = 0; j < 2; ++j)
#pragma unroll
            for (int e = 0; e < 4; ++e) acc[i][j][e] = 0.f;

#pragma unroll
    for (int ks = 0; ks < 4; ++ks) {        // k16 steps over K=64
        int kb = ks * 8;                    // 8 words per k16
        uint32_t af[4][4];
#pragma unroll
        for (int mt = 0; mt < 4; ++mt) {
            int row = wm * 64 + mt * 16 + g;
            af[mt][0] = As[row * 36 + kb + tg];
            af[mt][1] = As[(row + 8) * 36 + kb + tg];
            af[mt][2] = As[row * 36 + kb + tg + 4];
            af[mt][3] = As[(row + 8) * 36 + kb + tg + 4];
        }
        uint32_t bf[2][2];
#pragma unroll
        for (int nt = 0; nt < 2; ++nt) {
            int col = wn * 16 + nt * 8 + g;
            bf[nt][0] = Bs[col * 36 + kb + tg];
            bf[nt][1] = Bs[col * 36 + kb + tg + 4];
        }
#pragma unroll
        for (int mt = 0; mt < 4; ++mt)
#pragma unroll
            for (int nt = 0; nt < 2; ++nt)
                mma16(acc[mt][nt], af[mt], bf[nt]);
    }

    if (blockIdx.y < 2) {
        // Q/K: write fp16 [row][d] (pairs along d)
        __half* C = (blockIdx.y == 0) ? Qp : Kp;
        uint32_t* Cw = reinterpret_cast<uint32_t*>(C) + (long long)blockIdx.x * 128 * 32;
#pragma unroll
        for (int mt = 0; mt < 4; ++mt) {
            int row = wm * 64 + mt * 16 + g;
#pragma unroll
            for (int nt = 0; nt < 2; ++nt) {
                int colw = (wn * 16 + nt * 8 + 2 * tg) >> 1;  // word index
                Cw[row * 32 + colw]       = pack2(acc[mt][nt][0], acc[mt][nt][1]);
                Cw[(row + 8) * 32 + colw] = pack2(acc[mt][nt][2], acc[mt][nt][3]);
            }
        }
    } else {
        // V: write packed pairs along l into Vt: word idx = ((n*16+h)*512 + k0)*64 + d
        int f0 = blockIdx.x * 128;
        int n  = f0 >> 14;
        int l0 = (f0 >> 4) & 1023;
        uint32_t* Vw = reinterpret_cast<uint32_t*>(Vt);
#pragma unroll
        for (int pt = 0; pt < 2; ++pt) {
            int k0 = (l0 >> 1) + wm * 2 + pt;   // pair (l, l+1) = acc[2pt], acc[2pt+1]
#pragma unroll
            for (int nt = 0; nt < 2; ++nt) {
                int d = wn * 16 + nt * 8 + 2 * tg;
                // h = g (e0,e1) and h = g+8 (e2,e3)
                long long b0 = ((long long)(n * 16 + g) * 512 + k0) * 64 + d;
                long long b1 = ((long long)(n * 16 + g + 8) * 512 + k0) * 64 + d;
                uint2 u0 = make_uint2(pack2(acc[2 * pt][nt][0], acc[2 * pt + 1][nt][0]),
                                      pack2(acc[2 * pt][nt][1], acc[2 * pt + 1][nt][1]));
                uint2 u1 = make_uint2(pack2(acc[2 * pt][nt][2], acc[2 * pt + 1][nt][2]),
                                      pack2(acc[2 * pt][nt][3], acc[2 * pt + 1][nt][3]));
                *reinterpret_cast<uint2*>(Vw + b0) = u0;
                *reinterpret_cast<uint2*>(Vw + b1) = u1;
            }
        }
    }
}

// ===========================================================================
// Big GEMM: out[8192 x 1024] = AO[8192 x 1024] * Wt[1024 x 1024]^T, fp16 in,
// fp32 out. 128x128 tile, k-chunk 64, cp.async double buffer, 2 CTAs/SM.
// smem words: As 2*4608, Bs 2*4608 at 9216. 72 KB.
// ===========================================================================
__global__ __launch_bounds__(256, 2) void gemm_big(
    const __half* __restrict__ A, const __half* __restrict__ B,
    float* __restrict__ C)
{
    extern __shared__ uint32_t sm[];
    const uint32_t sbase = smem_u32(sm);

    const int t = threadIdx.x, lane = t & 31, wid = t >> 5;
    const int wm = wid & 1, wn = wid >> 1;
    const int g = lane >> 2, tg = lane & 3;

    A += (long long)blockIdx.x * 128 * 1024;
    B += (long long)blockIdx.y * 128 * 1024;
    C += (long long)blockIdx.x * 128 * 1024 + (long long)blockIdx.y * 128;

    float acc[4][4][4];
#pragma unroll
    for (int i = 0; i < 4; ++i)
#pragma unroll
        for (int j = 0; j < 4; ++j)
#pragma unroll
            for (int e = 0; e < 4; ++e) acc[i][j][e] = 0.f;

#pragma unroll
    for (int i = 0; i < 4; ++i) {
        int s = t + i * 256, r = s >> 3, ch = s & 7;   // 128 rows x 8 chunks(16B)
        cp16(sbase + (r * 36 + ch * 4) * 4, A + (long long)r * 1024 + ch * 8);
        cp16(sbase + (9216 + r * 36 + ch * 4) * 4, B + (long long)r * 1024 + ch * 8);
    }
    CP_COMMIT();

    for (int ck = 0; ck < 16; ++ck) {
        __syncthreads();
        if (ck < 15) {
            int kc = (ck + 1) * 64, b = (ck + 1) & 1;
#pragma unroll
            for (int i = 0; i < 4; ++i) {
                int s = t + i * 256, r = s >> 3, ch = s & 7;
                cp16(sbase + (b * 4608 + r * 36 + ch * 4) * 4,
                     A + (long long)r * 1024 + kc + ch * 8);
                cp16(sbase + (9216 + b * 4608 + r * 36 + ch * 4) * 4,
                     B + (long long)r * 1024 + kc + ch * 8);
            }
            CP_COMMIT();
            CP_WAIT(1);
        } else {
            CP_WAIT(0);
        }
        __syncthreads();

        const uint32_t* As = sm + (ck & 1) * 4608;
        const uint32_t* Bs = sm + 9216 + (ck & 1) * 4608;
#pragma unroll
        for (int ks = 0; ks < 4; ++ks) {
            int kb = ks * 8;
            uint32_t af[4][4];
#pragma unroll
            for (int mt = 0; mt < 4; ++mt) {
                int row = wm * 64 + mt * 16 + g;
                af[mt][0] = As[row * 36 + kb + tg];
                af[mt][1] = As[(row + 8) * 36 + kb + tg];
                af[mt][2] = As[row * 36 + kb + tg + 4];
                af[mt][3] = As[(row + 8) * 36 + kb + tg + 4];
            }
            uint32_t bf[4][2];
#pragma unroll
            for (int nt = 0; nt < 4; ++nt) {
                int col = wn * 32 + nt * 8 + g;
                bf[nt][0] = Bs[col * 36 + kb + tg];
                bf[nt][1] = Bs[col * 36 + kb + tg + 4];
            }
#pragma unroll
            for (int mt = 0; mt < 4; ++mt)
#pragma unroll
                for (int nt = 0; nt < 4; ++nt)
                    mma16(acc[mt][nt], af[mt], bf[nt]);
        }
    }

#pragma unroll
    for (int mt = 0; mt < 4; ++mt) {
        int row = wm * 64 + mt * 16 + g;
#pragma unroll
        for (int nt = 0; nt < 4; ++nt) {
            int col = wn * 32 + nt * 8 + 2 * tg;
            *reinterpret_cast<float2*>(C + (long long)row * 1024 + col) =
                make_float2(acc[mt][nt][0], acc[mt][nt][1]);
            *reinterpret_cast<float2*>(C + (long long)(row + 8) * 1024 + col) =
                make_float2(acc[mt][nt][2], acc[mt][nt][3]);
        }
    }
}

// ===========================================================================
// Flash attention, fp16 mma m16n8k16, BK=64 double-buffered, 2 CTAs/SM.
// 8 warps x 16 q-rows. P-frags packed straight from S C-frags (no shuffles).
// smem words: Qs 0 (128*36=4608), Ks 4608 + b*2304 (64*36),
//             Vs 9216 + b*2304 (32*72). Total 13824 w = 54 KB.
// ===========================================================================
__global__ __launch_bounds__(256, 2) void attn_tc(
    const __half* __restrict__ Qp, const __half* __restrict__ Kp,
    const __half* __restrict__ Vt, __half* __restrict__ AO)
{
    extern __shared__ uint32_t sm[];
    const uint32_t sbase = smem_u32(sm);

    const int t = threadIdx.x, lane = t & 31, wid = t >> 5;
    const int g = lane >> 2, tg = lane & 3;
    const int qt = blockIdx.x, h = blockIdx.y, n = blockIdx.z;

    const long long base = ((long long)n << 20) + h * 64;          // halves
    const __half* Qb = Qp + base + (long long)(qt * 128) * 1024;
    const __half* Vh = Vt + (((long long)(n * 16 + h) * 512) * 64) * 2;

    // prefetch Q [128 rows x 32 words] + K tile 0 [64x32w] + V tile 0 [32x64w]
#pragma unroll
    for (int i = 0; i < 4; ++i) {
        int s = t + i * 256, r = s >> 3, ch = s & 7;
        cp16(sbase + (r * 36 + ch * 4) * 4, Qb + (long long)r * 1024 + ch * 8);
    }
#pragma unroll
    for (int i = 0; i < 2; ++i) {
        int s = t + i * 256, r = s >> 3, ch = s & 7;
        cp16(sbase + (4608 + r * 36 + ch * 4) * 4, Kp + base + (long long)r * 1024 + ch * 8);
    }
#pragma unroll
    for (int i = 0; i < 2; ++i) {
        int s = t + i * 256, r = s >> 4, ch = s & 15;
        cp16(sbase + (9216 + r * 72 + ch * 4) * 4, Vh + ((long long)r * 64 + ch * 4) * 2);
    }
    CP_COMMIT();

    float Of[8][4];
    float lsum[2] = {0.f, 0.f};
#pragma unroll
    for (int dtl = 0; dtl < 8; ++dtl)
#pragma unroll
        for (int e = 0; e < 4; ++e) Of[dtl][e] = 0.f;

    const float CS = 0.03125f * 1.44269504088896f;   // 1/sqrt(1024) * log2(e)
    const int qrow = wid * 16 + g;

    for (int kt = 0; kt < 16; ++kt) {
        __syncthreads();
        if (kt < 15) {
            int b = (kt + 1) & 1;
            const __half* Kb = Kp + base + (long long)((kt + 1) * 64) * 1024;
            const __half* Vb = Vh + (long long)(kt + 1) * 32 * 64 * 2;
#pragma unroll
            for (int i = 0; i < 2; ++i) {
                int s = t + i * 256, r = s >> 3, ch = s & 7;
                cp16(sbase + (4608 + b * 2304 + r * 36 + ch * 4) * 4,
                     Kb + (long long)r * 1024 + ch * 8);
            }
#pragma unroll
            for (int i = 0; i < 2; ++i) {
                int s = t + i * 256, r = s >> 4, ch = s & 15;
                cp16(sbase + (9216 + b * 2304 + r * 72 + ch * 4) * 4,
                     Vb + ((long long)r * 64 + ch * 4) * 2);
            }
            CP_COMMIT();
            CP_WAIT(1);
        } else {
            CP_WAIT(0);
        }
        __syncthreads();

        const uint32_t* Qs = sm;
        const uint32_t* Ks = sm + 4608 + (kt & 1) * 2304;
        const uint32_t* Vs = sm + 9216 + (kt & 1) * 2304;

        // ---- S = Q K^T : warp tile 16q x 64k, 4 k16-steps ----
        float Sf[8][4];
#pragma unroll
        for (int nt = 0; nt < 8; ++nt)
#pragma unroll
            for (int e = 0; e < 4; ++e) Sf[nt][e] = 0.f;

#pragma unroll
        for (int ds = 0; ds < 4; ++ds) {
            int kb = ds * 8;
            uint32_t af[4];
            af[0] = Qs[qrow * 36 + kb + tg];
            af[1] = Qs[(qrow + 8) * 36 + kb + tg];
            af[2] = Qs[qrow * 36 + kb + tg + 4];
            af[3] = Qs[(qrow + 8) * 36 + kb + tg + 4];
#pragma unroll
            for (int nt = 0; nt < 8; ++nt) {
                int kr = nt * 8 + g;
                uint32_t bf[2];
                bf[0] = Ks[kr * 36 + kb + tg];
                bf[1] = Ks[kr * 36 + kb + tg + 4];
                mma16(Sf[nt], af, bf);
            }
        }

        // ---- P = exp2(S*CS); accumulate l ----
#pragma unroll
        for (int nt = 0; nt < 8; ++nt) {
            float e0 = ex2a(Sf[nt][0] * CS), e1 = ex2a(Sf[nt][1] * CS);
            float e2 = ex2a(Sf[nt][2] * CS), e3 = ex2a(Sf[nt][3] * CS);
            Sf[nt][0] = e0; Sf[nt][1] = e1; Sf[nt][2] = e2; Sf[nt][3] = e3;
            lsum[0] += e0 + e1;
            lsum[1] += e2 + e3;
        }

        // ---- O += P V : 4 k16-steps, P frag packed from S (no shuffles) ----
#pragma unroll
        for (int km = 0; km < 4; ++km) {
            uint32_t pa[4];
            pa[0] = pack2(Sf[2 * km][0],     Sf[2 * km][1]);
            pa[1] = pack2(Sf[2 * km][2],     Sf[2 * km][3]);
            pa[2] = pack2(Sf[2 * km + 1][0], Sf[2 * km + 1][1]);
            pa[3] = pack2(Sf[2 * km + 1][2], Sf[2 * km + 1][3]);
#pragma unroll
            for (int dtl = 0; dtl < 8; ++dtl) {
                uint32_t bf[2];
                bf[0] = Vs[(km * 8 + tg) * 72 + dtl * 8 + g];
                bf[1] = Vs[(km * 8 + tg + 4) * 72 + dtl * 8 + g];
                mma16(Of[dtl], pa, bf);
            }
        }
    }

    // ---- epilogue: quad-reduce l, normalize, write fp16 AO ----
    const unsigned FM = 0xffffffffu;
#pragma unroll
    for (int hh = 0; hh < 2; ++hh) {
        float v = lsum[hh];
        v += __shfl_xor_sync(FM, v, 1);
        v += __shfl_xor_sync(FM, v, 2);
        lsum[hh] = v;
    }
    float inv0 = 1.f / lsum[0], inv1 = 1.f / lsum[1];

    const int q0 = qt * 128 + qrow;
    uint32_t* Ob0 = reinterpret_cast<uint32_t*>(AO)
                  + (((long long)n * 1024 + q0) * 1024 + h * 64) / 2;
    uint32_t* Ob1 = reinterpret_cast<uint32_t*>(AO)
                  + (((long long)n * 1024 + q0 + 8) * 1024 + h * 64) / 2;
#pragma unroll
    for (int dtl = 0; dtl < 8; ++dtl) {
        int dw = (dtl * 8 + 2 * tg) >> 1;
        Ob0[dw] = pack2(Of[dtl][0] * inv0, Of[dtl][1] * inv0);
        Ob1[dw] = pack2(Of[dtl][2] * inv1, Of[dtl][3] * inv1);
    }
}

// ===========================================================================
extern "C" void kernel_launch(void* const* d_in, const int* in_sizes, int n_in,
                              void* d_out, int out_size)
{
    (void)in_sizes; (void)n_in; (void)out_size;
    const float* key   = (const float*)d_in[0];
    const float* query = (const float*)d_in[1];
    const float* value = (const float*)d_in[2];
    /* d_in[3] = mask — faithfully ignored (reference no-op) */
    const float* Wq = (const float*)d_in[4];
    const float* Wk = (const float*)d_in[5];
    const float* Wv = (const float*)d_in[6];
    const float* Wo = (const float*)d_in[7];
    float* out = (float*)d_out;

    __half *Qp, *Kp, *Vt, *AO, *Wt;
    cudaGetSymbolAddress((void**)&Qp, g_Qp);
    cudaGetSymbolAddress((void**)&Kp, g_Kp);
    cudaGetSymbolAddress((void**)&Vt, g_Vt);
    cudaGetSymbolAddress((void**)&AO, g_AO);
    cudaGetSymbolAddress((void**)&Wt, g_Wt);

    const int smem_proj = (128 * 36 + 64 * 36) * 4;   // 27648
    const int smem_big  = 18432 * 4;                  // 73728
    const int smem_attn = 13824 * 4;                  // 55296
    cudaFuncSetAttribute(proj_all,
        cudaFuncAttributeMaxDynamicSharedMemorySize, smem_proj);
    cudaFuncSetAttribute(gemm_big,
        cudaFuncAttributeMaxDynamicSharedMemorySize, smem_big);
    cudaFuncSetAttribute(attn_tc,
        cudaFuncAttributeMaxDynamicSharedMemorySize, smem_attn);

    dim3 blk(256);

    // Fused projections (y=0..2, V pre-packed along l) + Wo->fp16 (y=3)
    proj_all<<<dim3(1024, 4), blk, smem_proj>>>(
        query, key, value, Wq, Wk, Wv, Qp, Kp, Vt, Wo, Wt);

    // Attention: grid (q-tiles=8, heads=16, batch=8)
    attn_tc<<<dim3(8, NH, NB), blk, smem_attn>>>(Qp, Kp, Vt, AO);

    // Output projection: out = AO * Wt^T (fp16 in, fp32 out)
    gemm_big<<<dim3(64, 8), blk, smem_big>>>(AO, Wt, out);
}

// round 13
// speedup vs baseline: 1.9995x; 1.0284x over previous
#include <cuda_runtime.h>
#include <cuda_fp16.h>
#include <cstdint>

// Problem constants
#define NB   8
#define LSEQ 1024
#define EMB  1024
#define NH   16
#define HD   64

// Scratch (allocation-free rule: device globals) — fp16 intermediates
__device__ __half g_Qp[NB * LSEQ * EMB];
__device__ __half g_Kp[NB * LSEQ * EMB];
__device__ __half g_Vt[NB * LSEQ * EMB];   // V transposed: [(n*16+h)*64 + d][l]
__device__ __half g_AO[NB * LSEQ * EMB];
__device__ __half g_Wt[EMB * EMB];          // fp16 Wo

// ---------------------------------------------------------------------------
__device__ __forceinline__ uint32_t pack2(float lo, float hi) {
    __half2 h = __floats2half2_rn(lo, hi);
    return *reinterpret_cast<uint32_t*>(&h);
}
__device__ __forceinline__ float ex2a(float x) {
    float y;
    asm("ex2.approx.f32 %0, %1;" : "=f"(y) : "f"(x));
    return y;
}
__device__ __forceinline__ uint32_t smem_u32(const void* p) {
    uint32_t a;
    asm("{ .reg .u64 t; cvta.to.shared.u64 t, %1; cvt.u32.u64 %0, t; }"
        : "=r"(a) : "l"(p));
    return a;
}
__device__ __forceinline__ void cp16(uint32_t s, const void* g) {
    asm volatile("cp.async.cg.shared.global [%0], [%1], 16;" :: "r"(s), "l"(g));
}
#define CP_COMMIT() asm volatile("cp.async.commit_group;" ::: "memory")
#define CP_WAIT(n)  asm volatile("cp.async.wait_group %0;" :: "n"(n) : "memory")

// D += A*B, m16n8k16 fp16 inputs, fp32 accum.
__device__ __forceinline__ void mma16(float* d, const uint32_t* a, const uint32_t* b) {
    asm("mma.sync.aligned.m16n8k16.row.col.f32.f16.f16.f32 "
        "{%0,%1,%2,%3}, {%4,%5,%6,%7}, {%8,%9}, {%0,%1,%2,%3};"
        : "+f"(d[0]), "+f"(d[1]), "+f"(d[2]), "+f"(d[3])
        : "r"(a[0]), "r"(a[1]), "r"(a[2]), "r"(a[3]), "r"(b[0]), "r"(b[1]));
}
// ldmatrix x4: r[0..3] = matrices 0..3 (addresses: lanes 0-7 m0, 8-15 m1, ...)
__device__ __forceinline__ void ldsm4(uint32_t* r, uint32_t addr) {
    asm volatile("ldmatrix.sync.aligned.m8n8.x4.shared.b16 {%0,%1,%2,%3}, [%4];"
        : "=r"(r[0]), "=r"(r[1]), "=r"(r[2]), "=r"(r[3]) : "r"(addr));
}
// lane word-offsets for ldmatrix address (row pad = 36 words)
// A-type (a0..a3): m0 rows0-7/k0-7, m1 rows8-15/k0-7, m2 rows0-7/k8-15, m3 rows8-15/k8-15
__device__ __forceinline__ int laneA_off(int i) {
    return ((i & 7) + ((i >> 3) & 1) * 8) * 36 + ((i >> 4) & 1) * 4;
}
// B-type (b0,b1 of col-tile nt; then nt+1): m0 cols0-7/k0-7, m1 cols0-7/k8-15,
// m2 cols8-15/k0-7, m3 cols8-15/k8-15
__device__ __forceinline__ int laneB_off(int i) {
    return ((i & 7) + ((i >> 4) & 1) * 8) * 36 + ((i >> 3) & 1) * 4;
}

// ===========================================================================
// Fused front-end. blockIdx.y: 0=Q proj, 1=K proj, 2=V proj (transposed out),
// 3=Wo->fp16. Proj: C[128 x 64] = X[128 x 64] * W[64 x 64]^T.
// smem (words): As 128*36, Bs 64*36.
// ===========================================================================
__global__ __launch_bounds__(256) void proj_all(
    const float* __restrict__ q, const float* __restrict__ k,
    const float* __restrict__ v,
    const float* __restrict__ Wq, const float* __restrict__ Wk,
    const float* __restrict__ Wv,
    __half* __restrict__ Qp, __half* __restrict__ Kp, __half* __restrict__ Vt,
    const float* __restrict__ Wo, __half* __restrict__ Wt)
{
    const int t = threadIdx.x;
    if (blockIdx.y == 3) {
        int i = blockIdx.x * 256 + t;
        float4 w = reinterpret_cast<const float4*>(Wo)[i];
        uint2 u = make_uint2(pack2(w.x, w.y), pack2(w.z, w.w));
        *reinterpret_cast<uint2*>(reinterpret_cast<uint32_t*>(Wt) + i * 2) = u;
        return;
    }

    extern __shared__ uint32_t sm[];
    uint32_t* As = sm;            // [128][36] words
    uint32_t* Bs = sm + 128 * 36;

    const float* A = (blockIdx.y == 0) ? q : (blockIdx.y == 1) ? k : v;
    const float* B = (blockIdx.y == 0) ? Wq : (blockIdx.y == 1) ? Wk : Wv;

    const int lane = t & 31, wid = t >> 5;
    const int wm = wid & 1, wn = wid >> 1;
    const int g = lane >> 2, tg = lane & 3;

    A += (long long)blockIdx.x * 128 * 64;

#pragma unroll
    for (int i = 0; i < 8; ++i) {
        int s = t + i * 256, r = s >> 4, c4 = (s & 15) << 2;
        float4 vv = *reinterpret_cast<const float4*>(A + (long long)r * 64 + c4);
        uint2 u = make_uint2(pack2(vv.x, vv.y), pack2(vv.z, vv.w));
        *reinterpret_cast<uint2*>(&As[r * 36 + (c4 >> 1)]) = u;
    }
#pragma unroll
    for (int i = 0; i < 4; ++i) {
        int s = t + i * 256, r = s >> 4, c4 = (s & 15) << 2;
        float4 vv = *reinterpret_cast<const float4*>(B + (long long)r * 64 + c4);
        uint2 u = make_uint2(pack2(vv.x, vv.y), pack2(vv.z, vv.w));
        *reinterpret_cast<uint2*>(&Bs[r * 36 + (c4 >> 1)]) = u;
    }
    __syncthreads();

    float acc[4][2][4];
#pragma unroll
    for (int i = 0; i < 4; ++i)
#pragma unroll
        for (int j = 0; j < 2; ++j)
#pragma unroll
            for (int e = 0; e < 4; ++e) acc[i][j][e] = 0.f;

#pragma unroll
    for (int ks = 0; ks < 4; ++ks) {
        int kb = ks * 8;
        uint32_t af[4][4];
#pragma unroll
        for (int mt = 0; mt < 4; ++mt) {
            int row = wm * 64 + mt * 16 + g;
            af[mt][0] = As[row * 36 + kb + tg];
            af[mt][1] = As[(row + 8) * 36 + kb + tg];
            af[mt][2] = As[row * 36 + kb + tg + 4];
            af[mt][3] = As[(row + 8) * 36 + kb + tg + 4];
        }
        uint32_t bf[2][2];
#pragma unroll
        for (int nt = 0; nt < 2; ++nt) {
            int col = wn * 16 + nt * 8 + g;
            bf[nt][0] = Bs[col * 36 + kb + tg];
            bf[nt][1] = Bs[col * 36 + kb + tg + 4];
        }
#pragma unroll
        for (int mt = 0; mt < 4; ++mt)
#pragma unroll
            for (int nt = 0; nt < 2; ++nt)
                mma16(acc[mt][nt], af[mt], bf[nt]);
    }

    if (blockIdx.y < 2) {
        __half* C = (blockIdx.y == 0) ? Qp : Kp;
        uint32_t* Cw = reinterpret_cast<uint32_t*>(C) + (long long)blockIdx.x * 128 * 32;
#pragma unroll
        for (int mt = 0; mt < 4; ++mt) {
            int row = wm * 64 + mt * 16 + g;
#pragma unroll
            for (int nt = 0; nt < 2; ++nt) {
                int colw = (wn * 16 + nt * 8 + 2 * tg) >> 1;
                Cw[row * 32 + colw]       = pack2(acc[mt][nt][0], acc[mt][nt][1]);
                Cw[(row + 8) * 32 + colw] = pack2(acc[mt][nt][2], acc[mt][nt][3]);
            }
        }
    } else {
        // V: transpose via smem -> VtT[(n*16+h)*64 + d][l] coalesced 16B rows.
        __syncthreads();   // done reading As/Bs frags
        __half* Hs = reinterpret_cast<__half*>(sm);  // [128 r][72 halves] (=36 words/row)
#pragma unroll
        for (int mt = 0; mt < 4; ++mt) {
            int row = wm * 64 + mt * 16 + g;
#pragma unroll
            for (int nt = 0; nt < 2; ++nt) {
                int dw = (wn * 16 + nt * 8 + 2 * tg) >> 1;
                sm[row * 36 + dw]       = pack2(acc[mt][nt][0], acc[mt][nt][1]);
                sm[(row + 8) * 36 + dw] = pack2(acc[mt][nt][2], acc[mt][nt][3]);
            }
        }
        __syncthreads();
        int f0 = blockIdx.x * 128;
        int n  = f0 >> 14, l0 = (f0 >> 4) & 1023;
        uint32_t* Vw = reinterpret_cast<uint32_t*>(Vt);
        const uint16_t* Hh = reinterpret_cast<const uint16_t*>(Hs);
#pragma unroll
        for (int w = 0; w < 4; ++w) {
            int idx = t + w * 256;
            int hh = idx & 15, d = idx >> 4;
            uint32_t e01 = (uint32_t)Hh[(0 * 16 + hh) * 72 + d]
                         | ((uint32_t)Hh[(1 * 16 + hh) * 72 + d] << 16);
            uint32_t e23 = (uint32_t)Hh[(2 * 16 + hh) * 72 + d]
                         | ((uint32_t)Hh[(3 * 16 + hh) * 72 + d] << 16);
            uint32_t e45 = (uint32_t)Hh[(4 * 16 + hh) * 72 + d]
                         | ((uint32_t)Hh[(5 * 16 + hh) * 72 + d] << 16);
            uint32_t e67 = (uint32_t)Hh[(6 * 16 + hh) * 72 + d]
                         | ((uint32_t)Hh[(7 * 16 + hh) * 72 + d] << 16);
            long long wr = ((long long)(n * 16 + hh) * 64 + d) * 512 + (l0 >> 1);
            *reinterpret_cast<uint4*>(Vw + wr) = make_uint4(e01, e23, e45, e67);
        }
    }
}

// ===========================================================================
// Big GEMM: out[8192 x 1024] = AO * Wt^T, fp16 in, fp32 out. 128x128 tile,
// k-chunk 64, cp.async double buffer, ldmatrix frags, 2 CTAs/SM.
// ===========================================================================
__global__ __launch_bounds__(256, 2) void gemm_big(
    const __half* __restrict__ A, const __half* __restrict__ B,
    float* __restrict__ C)
{
    extern __shared__ uint32_t sm[];
    const uint32_t sbase = smem_u32(sm);

    const int t = threadIdx.x, lane = t & 31, wid = t >> 5;
    const int wm = wid & 1, wn = wid >> 1;
    const int g = lane >> 2, tg = lane & 3;
    const int lA = laneA_off(lane), lB = laneB_off(lane);

    A += (long long)blockIdx.x * 128 * 1024;
    B += (long long)blockIdx.y * 128 * 1024;
    C += (long long)blockIdx.x * 128 * 1024 + (long long)blockIdx.y * 128;

    float acc[4][4][4];
#pragma unroll
    for (int i = 0; i < 4; ++i)
#pragma unroll
        for (int j = 0; j < 4; ++j)
#pragma unroll
            for (int e = 0; e < 4; ++e) acc[i][j][e] = 0.f;

#pragma unroll
    for (int i = 0; i < 4; ++i) {
        int s = t + i * 256, r = s >> 3, ch = s & 7;
        cp16(sbase + (r * 36 + ch * 4) * 4, A + (long long)r * 1024 + ch * 8);
        cp16(sbase + (9216 + r * 36 + ch * 4) * 4, B + (long long)r * 1024 + ch * 8);
    }
    CP_COMMIT();

    for (int ck = 0; ck < 16; ++ck) {
        __syncthreads();
        if (ck < 15) {
            int kc = (ck + 1) * 64, b = (ck + 1) & 1;
#pragma unroll
            for (int i = 0; i < 4; ++i) {
                int s = t + i * 256, r = s >> 3, ch = s & 7;
                cp16(sbase + (b * 4608 + r * 36 + ch * 4) * 4,
                     A + (long long)r * 1024 + kc + ch * 8);
                cp16(sbase + (9216 + b * 4608 + r * 36 + ch * 4) * 4,
                     B + (long long)r * 1024 + kc + ch * 8);
            }
            CP_COMMIT();
            CP_WAIT(1);
        } else {
            CP_WAIT(0);
        }
        __syncthreads();

        const uint32_t Aad = sbase + ((ck & 1) * 4608 + wm * 64 * 36 + lA) * 4;
        const uint32_t Bad = sbase + (9216 + (ck & 1) * 4608 + wn * 32 * 36 + lB) * 4;
#pragma unroll
        for (int ks = 0; ks < 4; ++ks) {
            uint32_t af[4][4];
#pragma unroll
            for (int mt = 0; mt < 4; ++mt)
                ldsm4(af[mt], Aad + (mt * 16 * 36 + ks * 8) * 4);
            uint32_t bfp[2][4];
#pragma unroll
            for (int ntp = 0; ntp < 2; ++ntp)
                ldsm4(bfp[ntp], Bad + (ntp * 16 * 36 + ks * 8) * 4);
#pragma unroll
            for (int mt = 0; mt < 4; ++mt)
#pragma unroll
                for (int ntp = 0; ntp < 2; ++ntp) {
                    mma16(acc[mt][2 * ntp],     af[mt], &bfp[ntp][0]);
                    mma16(acc[mt][2 * ntp + 1], af[mt], &bfp[ntp][2]);
                }
        }
    }

#pragma unroll
    for (int mt = 0; mt < 4; ++mt) {
        int row = wm * 64 + mt * 16 + g;
#pragma unroll
        for (int nt = 0; nt < 4; ++nt) {
            int col = wn * 32 + nt * 8 + 2 * tg;
            *reinterpret_cast<float2*>(C + (long long)row * 1024 + col) =
                make_float2(acc[mt][nt][0], acc[mt][nt][1]);
            *reinterpret_cast<float2*>(C + (long long)(row + 8) * 1024 + col) =
                make_float2(acc[mt][nt][2], acc[mt][nt][3]);
        }
    }
}

// ===========================================================================
// Flash attention, fp16 mma m16n8k16, BK=64 double-buffered, 2 CTAs/SM.
// 8 warps x 16 q-rows. ldmatrix frags; Q A-frags hoisted (loop-invariant).
// smem words: Qs 0 (128*36), Ks 4608 + b*2304 (64*36), Vs 9216 + b*2304
//             (VsT: 64 d-rows * 36 words of k-halves). Total 13824 w = 54 KB.
// ===========================================================================
__global__ __launch_bounds__(256, 2) void attn_tc(
    const __half* __restrict__ Qp, const __half* __restrict__ Kp,
    const __half* __restrict__ Vt, __half* __restrict__ AO)
{
    extern __shared__ uint32_t sm[];
    const uint32_t sbase = smem_u32(sm);

    const int t = threadIdx.x, lane = t & 31, wid = t >> 5;
    const int g = lane >> 2, tg = lane & 3;
    const int lA = laneA_off(lane), lB = laneB_off(lane);
    const int qt = blockIdx.x, h = blockIdx.y, n = blockIdx.z;

    const long long base = ((long long)n << 20) + h * 64;          // halves
    const __half* Qb = Qp + base + (long long)(qt * 128) * 1024;
    const __half* Vh = Vt + ((long long)(n * 16 + h) * 64) * 1024; // VtT rows

    // prefetch Q [128r x 32w] + K tile0 [64r x 32w] + VsT tile0 [64d x 32w]
#pragma unroll
    for (int i = 0; i < 4; ++i) {
        int s = t + i * 256, r = s >> 3, ch = s & 7;
        cp16(sbase + (r * 36 + ch * 4) * 4, Qb + (long long)r * 1024 + ch * 8);
    }
#pragma unroll
    for (int i = 0; i < 2; ++i) {
        int s = t + i * 256, r = s >> 3, ch = s & 7;
        cp16(sbase + (4608 + r * 36 + ch * 4) * 4, Kp + base + (long long)r * 1024 + ch * 8);
        cp16(sbase + (9216 + r * 36 + ch * 4) * 4, Vh + (long long)r * 1024 + ch * 8);
    }
    CP_COMMIT();

    float Of[8][4];
    float lsum[2] = {0.f, 0.f};
#pragma unroll
    for (int dtl = 0; dtl < 8; ++dtl)
#pragma unroll
        for (int e = 0; e < 4; ++e) Of[dtl][e] = 0.f;

    uint32_t Qa[4][4];                               // hoisted Q A-frags
    const float CS = 0.03125f * 1.44269504088896f;   // 1/sqrt(1024) * log2(e)

    for (int kt = 0; kt < 16; ++kt) {
        __syncthreads();
        if (kt < 15) {
            int b = (kt + 1) & 1;
            const __half* Kb = Kp + base + (long long)((kt + 1) * 64) * 1024;
            const __half* Vb = Vh + (kt + 1) * 64;
#pragma unroll
            for (int i = 0; i < 2; ++i) {
                int s = t + i * 256, r = s >> 3, ch = s & 7;
                cp16(sbase + (4608 + b * 2304 + r * 36 + ch * 4) * 4,
                     Kb + (long long)r * 1024 + ch * 8);
                cp16(sbase + (9216 + b * 2304 + r * 36 + ch * 4) * 4,
                     Vb + (long long)r * 1024 + ch * 8);
            }
            CP_COMMIT();
            CP_WAIT(1);
        } else {
            CP_WAIT(0);
        }
        __syncthreads();

        if (kt == 0) {
            uint32_t Qad = sbase + (wid * 16 * 36 + lA) * 4;
#pragma unroll
            for (int ds = 0; ds < 4; ++ds)
                ldsm4(Qa[ds], Qad + ds * 8 * 4);
        }

        const uint32_t Kad = sbase + (4608 + (kt & 1) * 2304 + lB) * 4;
        const uint32_t Vad = sbase + (9216 + (kt & 1) * 2304 + lB) * 4;

        // ---- S = Q K^T : warp tile 16q x 64k ----
        float Sf[8][4];
#pragma unroll
        for (int nt = 0; nt < 8; ++nt)
#pragma unroll
            for (int e = 0; e < 4; ++e) Sf[nt][e] = 0.f;

#pragma unroll
        for (int ds = 0; ds < 4; ++ds) {
#pragma unroll
            for (int ntp = 0; ntp < 4; ++ntp) {
                uint32_t bf[4];
                ldsm4(bf, Kad + (ntp * 16 * 36 + ds * 8) * 4);
                mma16(Sf[2 * ntp],     Qa[ds], &bf[0]);
                mma16(Sf[2 * ntp + 1], Qa[ds], &bf[2]);
            }
        }

        // ---- P = exp2(S*CS); accumulate l ----
#pragma unroll
        for (int nt = 0; nt < 8; ++nt) {
            float e0 = ex2a(Sf[nt][0] * CS), e1 = ex2a(Sf[nt][1] * CS);
            float e2 = ex2a(Sf[nt][2] * CS), e3 = ex2a(Sf[nt][3] * CS);
            Sf[nt][0] = e0; Sf[nt][1] = e1; Sf[nt][2] = e2; Sf[nt][3] = e3;
            lsum[0] += e0 + e1;
            lsum[1] += e2 + e3;
        }

        // ---- O += P V ----
#pragma unroll
        for (int km = 0; km < 4; ++km) {
            uint32_t pa[4];
            pa[0] = pack2(Sf[2 * km][0],     Sf[2 * km][1]);
            pa[1] = pack2(Sf[2 * km][2],     Sf[2 * km][3]);
            pa[2] = pack2(Sf[2 * km + 1][0], Sf[2 * km + 1][1]);
            pa[3] = pack2(Sf[2 * km + 1][2], Sf[2 * km + 1][3]);
#pragma unroll
            for (int dtlp = 0; dtlp < 4; ++dtlp) {
                uint32_t bf[4];
                ldsm4(bf, Vad + (dtlp * 16 * 36 + km * 8) * 4);
                mma16(Of[2 * dtlp],     pa, &bf[0]);
                mma16(Of[2 * dtlp + 1], pa, &bf[2]);
            }
        }
    }

    // ---- epilogue: quad-reduce l, normalize, write fp16 AO ----
    const unsigned FM = 0xffffffffu;
#pragma unroll
    for (int hh = 0; hh < 2; ++hh) {
        float v = lsum[hh];
        v += __shfl_xor_sync(FM, v, 1);
        v += __shfl_xor_sync(FM, v, 2);
        lsum[hh] = v;
    }
    float inv0 = 1.f / lsum[0], inv1 = 1.f / lsum[1];

    const int q0 = qt * 128 + wid * 16 + g;
    uint32_t* Ob0 = reinterpret_cast<uint32_t*>(AO)
                  + (((long long)n * 1024 + q0) * 1024 + h * 64) / 2;
    uint32_t* Ob1 = reinterpret_cast<uint32_t*>(AO)
                  + (((long long)n * 1024 + q0 + 8) * 1024 + h * 64) / 2;
#pragma unroll
    for (int dtl = 0; dtl < 8; ++dtl) {
        int dw = (dtl * 8 + 2 * tg) >> 1;
        Ob0[dw] = pack2(Of[dtl][0] * inv0, Of[dtl][1] * inv0);
        Ob1[dw] = pack2(Of[dtl][2] * inv1, Of[dtl][3] * inv1);
    }
}

// ===========================================================================
extern "C" void kernel_launch(void* const* d_in, const int* in_sizes, int n_in,
                              void* d_out, int out_size)
{
    (void)in_sizes; (void)n_in; (void)out_size;
    const float* key   = (const float*)d_in[0];
    const float* query = (const float*)d_in[1];
    const float* value = (const float*)d_in[2];
    /* d_in[3] = mask — faithfully ignored (reference no-op) */
    const float* Wq = (const float*)d_in[4];
    const float* Wk = (const float*)d_in[5];
    const float* Wv = (const float*)d_in[6];
    const float* Wo = (const float*)d_in[7];
    float* out = (float*)d_out;

    __half *Qp, *Kp, *Vt, *AO, *Wt;
    cudaGetSymbolAddress((void**)&Qp, g_Qp);
    cudaGetSymbolAddress((void**)&Kp, g_Kp);
    cudaGetSymbolAddress((void**)&Vt, g_Vt);
    cudaGetSymbolAddress((void**)&AO, g_AO);
    cudaGetSymbolAddress((void**)&Wt, g_Wt);

    const int smem_proj = (128 * 36 + 64 * 36) * 4;   // 27648
    const int smem_big  = 18432 * 4;                  // 73728
    const int smem_attn = 13824 * 4;                  // 55296
    cudaFuncSetAttribute(proj_all,
        cudaFuncAttributeMaxDynamicSharedMemorySize, smem_proj);
    cudaFuncSetAttribute(gemm_big,
        cudaFuncAttributeMaxDynamicSharedMemorySize, smem_big);
    cudaFuncSetAttribute(attn_tc,
        cudaFuncAttributeMaxDynamicSharedMemorySize, smem_attn);

    dim3 blk(256);

    // Fused projections (y=0..2, V written transposed) + Wo->fp16 (y=3)
    proj_all<<<dim3(1024, 4), blk, smem_proj>>>(
        query, key, value, Wq, Wk, Wv, Qp, Kp, Vt, Wo, Wt);

    // Attention: grid (q-tiles=8, heads=16, batch=8)
    attn_tc<<<dim3(8, NH, NB), blk, smem_attn>>>(Qp, Kp, Vt, AO);

    // Output projection: out = AO * Wt^T (fp16 in, fp32 out)
    gemm_big<<<dim3(64, 8), blk, smem_big>>>(AO, Wt, out);
}

// round 14
// speedup vs baseline: 2.0808x; 1.0406x over previous
#include <cuda_runtime.h>
#include <cuda_fp16.h>
#include <cstdint>

// Problem constants
#define NB   8
#define LSEQ 1024
#define EMB  1024
#define NH   16
#define HD   64

// Scratch (allocation-free rule: device globals) — fp16 intermediates
__device__ __half g_Qp[NB * LSEQ * EMB];
__device__ __half g_Kp[NB * LSEQ * EMB];
__device__ __half g_Vp[NB * LSEQ * EMB];   // V natural [n,l,h,d] (same as K)
__device__ __half g_AO[NB * LSEQ * EMB];
__device__ __half g_Wt[EMB * EMB];          // fp16 Wo

// ---------------------------------------------------------------------------
__device__ __forceinline__ uint32_t pack2(float lo, float hi) {
    __half2 h = __floats2half2_rn(lo, hi);
    return *reinterpret_cast<uint32_t*>(&h);
}
__device__ __forceinline__ uint32_t h2exp2w(uint32_t x) {
    uint32_t y;
    asm("ex2.approx.f16x2 %0, %1;" : "=r"(y) : "r"(x));
    return y;
}
__device__ __forceinline__ uint32_t smem_u32(const void* p) {
    uint32_t a;
    asm("{ .reg .u64 t; cvta.to.shared.u64 t, %1; cvt.u32.u64 %0, t; }"
        : "=r"(a) : "l"(p));
    return a;
}
__device__ __forceinline__ void cp16(uint32_t s, const void* g) {
    asm volatile("cp.async.cg.shared.global [%0], [%1], 16;" :: "r"(s), "l"(g));
}
#define CP_COMMIT() asm volatile("cp.async.commit_group;" ::: "memory")
#define CP_WAIT(n)  asm volatile("cp.async.wait_group %0;" :: "n"(n) : "memory")

// D += A*B, m16n8k16 fp16 inputs, fp32 accum.
__device__ __forceinline__ void mma16(float* d, const uint32_t* a, const uint32_t* b) {
    asm("mma.sync.aligned.m16n8k16.row.col.f32.f16.f16.f32 "
        "{%0,%1,%2,%3}, {%4,%5,%6,%7}, {%8,%9}, {%0,%1,%2,%3};"
        : "+f"(d[0]), "+f"(d[1]), "+f"(d[2]), "+f"(d[3])
        : "r"(a[0]), "r"(a[1]), "r"(a[2]), "r"(a[3]), "r"(b[0]), "r"(b[1]));
}
__device__ __forceinline__ void ldsm4(uint32_t* r, uint32_t addr) {
    asm volatile("ldmatrix.sync.aligned.m8n8.x4.shared.b16 {%0,%1,%2,%3}, [%4];"
        : "=r"(r[0]), "=r"(r[1]), "=r"(r[2]), "=r"(r[3]) : "r"(addr));
}
__device__ __forceinline__ void ldsm4t(uint32_t* r, uint32_t addr) {
    asm volatile("ldmatrix.sync.aligned.m8n8.x4.trans.shared.b16 {%0,%1,%2,%3}, [%4];"
        : "=r"(r[0]), "=r"(r[1]), "=r"(r[2]), "=r"(r[3]) : "r"(addr));
}
// lane word-offsets for ldmatrix addressing (row pad = 36 words)
// A-type / trans-V: m-index bits: i&7 row, (i>>3)&1 row+8, (i>>4)&1 col-word+4
__device__ __forceinline__ int laneA_off(int i) {
    return ((i & 7) + ((i >> 3) & 1) * 8) * 36 + ((i >> 4) & 1) * 4;
}
// B-type (K, Wt): (i>>4)&1 row+8, (i>>3)&1 col-word+4
__device__ __forceinline__ int laneB_off(int i) {
    return ((i & 7) + ((i >> 4) & 1) * 8) * 36 + ((i >> 3) & 1) * 4;
}

// ===========================================================================
// Fused front-end. blockIdx.y: 0=Q, 1=K, 2=V projection (all identical paths),
// 3=Wo->fp16. Proj: C[128 x 64] = X[128 x 64] * W[64 x 64]^T.
// smem (words): As 128*36, Bs 64*36.
// ===========================================================================
__global__ __launch_bounds__(256) void proj_all(
    const float* __restrict__ q, const float* __restrict__ k,
    const float* __restrict__ v,
    const float* __restrict__ Wq, const float* __restrict__ Wk,
    const float* __restrict__ Wv,
    __half* __restrict__ Qp, __half* __restrict__ Kp, __half* __restrict__ Vp,
    const float* __restrict__ Wo, __half* __restrict__ Wt)
{
    const int t = threadIdx.x;
    if (blockIdx.y == 3) {
        int i = blockIdx.x * 256 + t;
        float4 w = reinterpret_cast<const float4*>(Wo)[i];
        uint2 u = make_uint2(pack2(w.x, w.y), pack2(w.z, w.w));
        *reinterpret_cast<uint2*>(reinterpret_cast<uint32_t*>(Wt) + i * 2) = u;
        return;
    }

    extern __shared__ uint32_t sm[];
    uint32_t* As = sm;            // [128][36] words
    uint32_t* Bs = sm + 128 * 36;

    const float* A = (blockIdx.y == 0) ? q : (blockIdx.y == 1) ? k : v;
    const float* B = (blockIdx.y == 0) ? Wq : (blockIdx.y == 1) ? Wk : Wv;
    __half* C = (blockIdx.y == 0) ? Qp : (blockIdx.y == 1) ? Kp : Vp;

    const int lane = t & 31, wid = t >> 5;
    const int wm = wid & 1, wn = wid >> 1;
    const int g = lane >> 2, tg = lane & 3;

    A += (long long)blockIdx.x * 128 * 64;

#pragma unroll
    for (int i = 0; i < 8; ++i) {
        int s = t + i * 256, r = s >> 4, c4 = (s & 15) << 2;
        float4 vv = *reinterpret_cast<const float4*>(A + (long long)r * 64 + c4);
        uint2 u = make_uint2(pack2(vv.x, vv.y), pack2(vv.z, vv.w));
        *reinterpret_cast<uint2*>(&As[r * 36 + (c4 >> 1)]) = u;
    }
#pragma unroll
    for (int i = 0; i < 4; ++i) {
        int s = t + i * 256, r = s >> 4, c4 = (s & 15) << 2;
        float4 vv = *reinterpret_cast<const float4*>(B + (long long)r * 64 + c4);
        uint2 u = make_uint2(pack2(vv.x, vv.y), pack2(vv.z, vv.w));
        *reinterpret_cast<uint2*>(&Bs[r * 36 + (c4 >> 1)]) = u;
    }
    __syncthreads();

    float acc[4][2][4];
#pragma unroll
    for (int i = 0; i < 4; ++i)
#pragma unroll
        for (int j = 0; j < 2; ++j)
#pragma unroll
            for (int e = 0; e < 4; ++e) acc[i][j][e] = 0.f;

#pragma unroll
    for (int ks = 0; ks < 4; ++ks) {
        int kb = ks * 8;
        uint32_t af[4][4];
#pragma unroll
        for (int mt = 0; mt < 4; ++mt) {
            int row = wm * 64 + mt * 16 + g;
            af[mt][0] = As[row * 36 + kb + tg];
            af[mt][1] = As[(row + 8) * 36 + kb + tg];
            af[mt][2] = As[row * 36 + kb + tg + 4];
            af[mt][3] = As[(row + 8) * 36 + kb + tg + 4];
        }
        uint32_t bf[2][2];
#pragma unroll
        for (int nt = 0; nt < 2; ++nt) {
            int col = wn * 16 + nt * 8 + g;
            bf[nt][0] = Bs[col * 36 + kb + tg];
            bf[nt][1] = Bs[col * 36 + kb + tg + 4];
        }
#pragma unroll
        for (int mt = 0; mt < 4; ++mt)
#pragma unroll
            for (int nt = 0; nt < 2; ++nt)
                mma16(acc[mt][nt], af[mt], bf[nt]);
    }

    uint32_t* Cw = reinterpret_cast<uint32_t*>(C) + (long long)blockIdx.x * 128 * 32;
#pragma unroll
    for (int mt = 0; mt < 4; ++mt) {
        int row = wm * 64 + mt * 16 + g;
#pragma unroll
        for (int nt = 0; nt < 2; ++nt) {
            int colw = (wn * 16 + nt * 8 + 2 * tg) >> 1;
            Cw[row * 32 + colw]       = pack2(acc[mt][nt][0], acc[mt][nt][1]);
            Cw[(row + 8) * 32 + colw] = pack2(acc[mt][nt][2], acc[mt][nt][3]);
        }
    }
}

// ===========================================================================
// Big GEMM: out[8192 x 1024] = AO * Wt^T, fp16 in, fp32 out. 128x128 tile,
// k-chunk 64, cp.async double buffer, ldmatrix frags, 2 CTAs/SM.
// ===========================================================================
__global__ __launch_bounds__(256, 2) void gemm_big(
    const __half* __restrict__ A, const __half* __restrict__ B,
    float* __restrict__ C)
{
    extern __shared__ uint32_t sm[];
    const uint32_t sbase = smem_u32(sm);

    const int t = threadIdx.x, lane = t & 31, wid = t >> 5;
    const int wm = wid & 1, wn = wid >> 1;
    const int g = lane >> 2, tg = lane & 3;
    const int lA = laneA_off(lane), lB = laneB_off(lane);

    A += (long long)blockIdx.x * 128 * 1024;
    B += (long long)blockIdx.y * 128 * 1024;
    C += (long long)blockIdx.x * 128 * 1024 + (long long)blockIdx.y * 128;

    float acc[4][4][4];
#pragma unroll
    for (int i = 0; i < 4; ++i)
#pragma unroll
        for (int j = 0; j < 4; ++j)
#pragma unroll
            for (int e = 0; e < 4; ++e) acc[i][j][e] = 0.f;

#pragma unroll
    for (int i = 0; i < 4; ++i) {
        int s = t + i * 256, r = s >> 3, ch = s & 7;
        cp16(sbase + (r * 36 + ch * 4) * 4, A + (long long)r * 1024 + ch * 8);
        cp16(sbase + (9216 + r * 36 + ch * 4) * 4, B + (long long)r * 1024 + ch * 8);
    }
    CP_COMMIT();

    for (int ck = 0; ck < 16; ++ck) {
        __syncthreads();
        if (ck < 15) {
            int kc = (ck + 1) * 64, b = (ck + 1) & 1;
#pragma unroll
            for (int i = 0; i < 4; ++i) {
                int s = t + i * 256, r = s >> 3, ch = s & 7;
                cp16(sbase + (b * 4608 + r * 36 + ch * 4) * 4,
                     A + (long long)r * 1024 + kc + ch * 8);
                cp16(sbase + (9216 + b * 4608 + r * 36 + ch * 4) * 4,
                     B + (long long)r * 1024 + kc + ch * 8);
            }
            CP_COMMIT();
            CP_WAIT(1);
        } else {
            CP_WAIT(0);
        }
        __syncthreads();

        const uint32_t Aad = sbase + ((ck & 1) * 4608 + wm * 64 * 36 + lA) * 4;
        const uint32_t Bad = sbase + (9216 + (ck & 1) * 4608 + wn * 32 * 36 + lB) * 4;
#pragma unroll
        for (int ks = 0; ks < 4; ++ks) {
            uint32_t af[4][4];
#pragma unroll
            for (int mt = 0; mt < 4; ++mt)
                ldsm4(af[mt], Aad + (mt * 16 * 36 + ks * 8) * 4);
            uint32_t bfp[2][4];
#pragma unroll
            for (int ntp = 0; ntp < 2; ++ntp)
                ldsm4(bfp[ntp], Bad + (ntp * 16 * 36 + ks * 8) * 4);
#pragma unroll
            for (int mt = 0; mt < 4; ++mt)
#pragma unroll
                for (int ntp = 0; ntp < 2; ++ntp) {
                    mma16(acc[mt][2 * ntp],     af[mt], &bfp[ntp][0]);
                    mma16(acc[mt][2 * ntp + 1], af[mt], &bfp[ntp][2]);
                }
        }
    }

#pragma unroll
    for (int mt = 0; mt < 4; ++mt) {
        int row = wm * 64 + mt * 16 + g;
#pragma unroll
        for (int nt = 0; nt < 4; ++nt) {
            int col = wn * 32 + nt * 8 + 2 * tg;
            *reinterpret_cast<float2*>(C + (long long)row * 1024 + col) =
                make_float2(acc[mt][nt][0], acc[mt][nt][1]);
            *reinterpret_cast<float2*>(C + (long long)(row + 8) * 1024 + col) =
                make_float2(acc[mt][nt][2], acc[mt][nt][3]);
        }
    }
}

// ===========================================================================
// Flash attention, fp16 mma m16n8k16, BK=64 double-buffered, 2 CTAs/SM.
// 8 warps x 16 q-rows. K natural + ldmatrix; V natural + ldmatrix.trans.
// P = ex2.approx.f16x2; row-sums via ones-B-frag mma (no FADD chain, no
// shuffles). smem words: Qs 0 (128*36), Ks 4608 + b*2304, Vs 9216 + b*2304.
// ===========================================================================
__global__ __launch_bounds__(256, 2) void attn_tc(
    const __half* __restrict__ Qp, const __half* __restrict__ Kp,
    const __half* __restrict__ Vp, __half* __restrict__ AO)
{
    extern __shared__ uint32_t sm[];
    const uint32_t sbase = smem_u32(sm);

    const int t = threadIdx.x, lane = t & 31, wid = t >> 5;
    const int g = lane >> 2, tg = lane & 3;
    const int lA = laneA_off(lane), lB = laneB_off(lane);
    const int qt = blockIdx.x, h = blockIdx.y, n = blockIdx.z;

    const long long base = ((long long)n << 20) + h * 64;          // halves
    const __half* Qb = Qp + base + (long long)(qt * 128) * 1024;

    // prefetch Q [128r x 32w] + K/V tile0 [64r x 32w each]
#pragma unroll
    for (int i = 0; i < 4; ++i) {
        int s = t + i * 256, r = s >> 3, ch = s & 7;
        cp16(sbase + (r * 36 + ch * 4) * 4, Qb + (long long)r * 1024 + ch * 8);
    }
#pragma unroll
    for (int i = 0; i < 2; ++i) {
        int s = t + i * 256, r = s >> 3, ch = s & 7;
        cp16(sbase + (4608 + r * 36 + ch * 4) * 4, Kp + base + (long long)r * 1024 + ch * 8);
        cp16(sbase + (9216 + r * 36 + ch * 4) * 4, Vp + base + (long long)r * 1024 + ch * 8);
    }
    CP_COMMIT();

    float Of[8][4];
    float Osum[4] = {0.f, 0.f, 0.f, 0.f};
#pragma unroll
    for (int dtl = 0; dtl < 8; ++dtl)
#pragma unroll
        for (int e = 0; e < 4; ++e) Of[dtl][e] = 0.f;

    uint32_t Qa[4][4];                               // hoisted Q A-frags
    const float CS = 0.03125f * 1.44269504088896f;   // 1/sqrt(1024) * log2(e)
    const uint32_t ONES2[2] = {0x3C003C00u, 0x3C003C00u};

    for (int kt = 0; kt < 16; ++kt) {
        __syncthreads();
        if (kt < 15) {
            int b = (kt + 1) & 1;
            const __half* Kb = Kp + base + (long long)((kt + 1) * 64) * 1024;
            const __half* Vb = Vp + base + (long long)((kt + 1) * 64) * 1024;
#pragma unroll
            for (int i = 0; i < 2; ++i) {
                int s = t + i * 256, r = s >> 3, ch = s & 7;
                cp16(sbase + (4608 + b * 2304 + r * 36 + ch * 4) * 4,
                     Kb + (long long)r * 1024 + ch * 8);
                cp16(sbase + (9216 + b * 2304 + r * 36 + ch * 4) * 4,
                     Vb + (long long)r * 1024 + ch * 8);
            }
            CP_COMMIT();
            CP_WAIT(1);
        } else {
            CP_WAIT(0);
        }
        __syncthreads();

        if (kt == 0) {
            uint32_t Qad = sbase + (wid * 16 * 36 + lA) * 4;
#pragma unroll
            for (int ds = 0; ds < 4; ++ds)
                ldsm4(Qa[ds], Qad + ds * 8 * 4);
        }

        const uint32_t Kad = sbase + (4608 + (kt & 1) * 2304 + lB) * 4;
        const uint32_t Vad = sbase + (9216 + (kt & 1) * 2304 + lA) * 4;

        // ---- S = Q K^T : warp tile 16q x 64k ----
        float Sf[8][4];
#pragma unroll
        for (int nt = 0; nt < 8; ++nt)
#pragma unroll
            for (int e = 0; e < 4; ++e) Sf[nt][e] = 0.f;

#pragma unroll
        for (int ds = 0; ds < 4; ++ds) {
#pragma unroll
            for (int ntp = 0; ntp < 4; ++ntp) {
                uint32_t bf[4];
                ldsm4(bf, Kad + (ntp * 16 * 36 + ds * 8) * 4);
                mma16(Sf[2 * ntp],     Qa[ds], &bf[0]);
                mma16(Sf[2 * ntp + 1], Qa[ds], &bf[2]);
            }
        }

        // ---- per km: P = exp2f16(S*CS); lsum via ones-mma; O += P V ----
#pragma unroll
        for (int km = 0; km < 4; ++km) {
            uint32_t pa[4];
            pa[0] = h2exp2w(pack2(Sf[2 * km][0] * CS,     Sf[2 * km][1] * CS));
            pa[1] = h2exp2w(pack2(Sf[2 * km][2] * CS,     Sf[2 * km][3] * CS));
            pa[2] = h2exp2w(pack2(Sf[2 * km + 1][0] * CS, Sf[2 * km + 1][1] * CS));
            pa[3] = h2exp2w(pack2(Sf[2 * km + 1][2] * CS, Sf[2 * km + 1][3] * CS));
            mma16(Osum, pa, ONES2);   // row-sums of P (all 8 cols identical)
#pragma unroll
            for (int dp = 0; dp < 4; ++dp) {
                uint32_t bf[4];
                ldsm4t(bf, Vad + (km * 16 * 36 + dp * 8) * 4);
                mma16(Of[2 * dp],     pa, &bf[0]);
                mma16(Of[2 * dp + 1], pa, &bf[2]);
            }
        }
    }

    // ---- epilogue: normalize (Osum c0 = row g sum, c2 = row g+8), write ----
    float inv0 = 1.f / Osum[0], inv1 = 1.f / Osum[2];

    const int q0 = qt * 128 + wid * 16 + g;
    uint32_t* Ob0 = reinterpret_cast<uint32_t*>(AO)
                  + (((long long)n * 1024 + q0) * 1024 + h * 64) / 2;
    uint32_t* Ob1 = reinterpret_cast<uint32_t*>(AO)
                  + (((long long)n * 1024 + q0 + 8) * 1024 + h * 64) / 2;
#pragma unroll
    for (int dtl = 0; dtl < 8; ++dtl) {
        int dw = (dtl * 8 + 2 * tg) >> 1;
        Ob0[dw] = pack2(Of[dtl][0] * inv0, Of[dtl][1] * inv0);
        Ob1[dw] = pack2(Of[dtl][2] * inv1, Of[dtl][3] * inv1);
    }
}

// ===========================================================================
extern "C" void kernel_launch(void* const* d_in, const int* in_sizes, int n_in,
                              void* d_out, int out_size)
{
    (void)in_sizes; (void)n_in; (void)out_size;
    const float* key   = (const float*)d_in[0];
    const float* query = (const float*)d_in[1];
    const float* value = (const float*)d_in[2];
    /* d_in[3] = mask — faithfully ignored (reference no-op) */
    const float* Wq = (const float*)d_in[4];
    const float* Wk = (const float*)d_in[5];
    const float* Wv = (const float*)d_in[6];
    const float* Wo = (const float*)d_in[7];
    float* out = (float*)d_out;

    __half *Qp, *Kp, *Vp, *AO, *Wt;
    cudaGetSymbolAddress((void**)&Qp, g_Qp);
    cudaGetSymbolAddress((void**)&Kp, g_Kp);
    cudaGetSymbolAddress((void**)&Vp, g_Vp);
    cudaGetSymbolAddress((void**)&AO, g_AO);
    cudaGetSymbolAddress((void**)&Wt, g_Wt);

    const int smem_proj = (128 * 36 + 64 * 36) * 4;   // 27648
    const int smem_big  = 18432 * 4;                  // 73728
    const int smem_attn = 13824 * 4;                  // 55296
    cudaFuncSetAttribute(proj_all,
        cudaFuncAttributeMaxDynamicSharedMemorySize, smem_proj);
    cudaFuncSetAttribute(gemm_big,
        cudaFuncAttributeMaxDynamicSharedMemorySize, smem_big);
    cudaFuncSetAttribute(attn_tc,
        cudaFuncAttributeMaxDynamicSharedMemorySize, smem_attn);

    dim3 blk(256);

    // Fused projections (y=0..2, all natural layout) + Wo->fp16 (y=3)
    proj_all<<<dim3(1024, 4), blk, smem_proj>>>(
        query, key, value, Wq, Wk, Wv, Qp, Kp, Vp, Wo, Wt);

    // Attention: grid (q-tiles=8, heads=16, batch=8)
    attn_tc<<<dim3(8, NH, NB), blk, smem_attn>>>(Qp, Kp, Vp, AO);

    // Output projection: out = AO * Wt^T (fp16 in, fp32 out)
    gemm_big<<<dim3(64, 8), blk, smem_big>>>(AO, Wt, out);
}

// round 15
// speedup vs baseline: 2.1936x; 1.0542x over previous
#include <cuda_runtime.h>
#include <cuda_fp16.h>
#include <cstdint>

// Problem constants
#define NB   8
#define LSEQ 1024
#define EMB  1024
#define NH   16
#define HD   64

// Scratch (allocation-free rule: device globals) — fp16 intermediates
__device__ __half g_Qp[NB * LSEQ * EMB];
__device__ __half g_Kp[NB * LSEQ * EMB];
__device__ __half g_Vp[NB * LSEQ * EMB];   // V natural [n,l,h,d] (same as K)
__device__ __half g_AO[NB * LSEQ * EMB];
__device__ __half g_Wt[EMB * EMB];          // fp16 Wo

// ---------------------------------------------------------------------------
__device__ __forceinline__ uint32_t pack2(float lo, float hi) {
    __half2 h = __floats2half2_rn(lo, hi);
    return *reinterpret_cast<uint32_t*>(&h);
}
__device__ __forceinline__ uint32_t h2exp2w(uint32_t x) {
    uint32_t y;
    asm("ex2.approx.f16x2 %0, %1;" : "=r"(y) : "r"(x));
    return y;
}
__device__ __forceinline__ uint32_t smem_u32(const void* p) {
    uint32_t a;
    asm("{ .reg .u64 t; cvta.to.shared.u64 t, %1; cvt.u32.u64 %0, t; }"
        : "=r"(a) : "l"(p));
    return a;
}
__device__ __forceinline__ void cp16(uint32_t s, const void* g) {
    asm volatile("cp.async.cg.shared.global [%0], [%1], 16;" :: "r"(s), "l"(g));
}
#define CP_COMMIT() asm volatile("cp.async.commit_group;" ::: "memory")
#define CP_WAIT(n)  asm volatile("cp.async.wait_group %0;" :: "n"(n) : "memory")

// D += A*B, m16n8k16 fp16 inputs, fp32 accum.
__device__ __forceinline__ void mma16(float* d, const uint32_t* a, const uint32_t* b) {
    asm("mma.sync.aligned.m16n8k16.row.col.f32.f16.f16.f32 "
        "{%0,%1,%2,%3}, {%4,%5,%6,%7}, {%8,%9}, {%0,%1,%2,%3};"
        : "+f"(d[0]), "+f"(d[1]), "+f"(d[2]), "+f"(d[3])
        : "r"(a[0]), "r"(a[1]), "r"(a[2]), "r"(a[3]), "r"(b[0]), "r"(b[1]));
}
__device__ __forceinline__ void ldsm4(uint32_t* r, uint32_t addr) {
    asm volatile("ldmatrix.sync.aligned.m8n8.x4.shared.b16 {%0,%1,%2,%3}, [%4];"
        : "=r"(r[0]), "=r"(r[1]), "=r"(r[2]), "=r"(r[3]) : "r"(addr));
}
__device__ __forceinline__ void ldsm4t(uint32_t* r, uint32_t addr) {
    asm volatile("ldmatrix.sync.aligned.m8n8.x4.trans.shared.b16 {%0,%1,%2,%3}, [%4];"
        : "=r"(r[0]), "=r"(r[1]), "=r"(r[2]), "=r"(r[3]) : "r"(addr));
}
// lane word-offsets for ldmatrix addressing (row pad = 36 words)
__device__ __forceinline__ int laneA_off(int i) {
    return ((i & 7) + ((i >> 3) & 1) * 8) * 36 + ((i >> 4) & 1) * 4;
}
__device__ __forceinline__ int laneB_off(int i) {
    return ((i & 7) + ((i >> 4) & 1) * 8) * 36 + ((i >> 3) & 1) * 4;
}

// ===========================================================================
// Fused front-end. blockIdx.y: 0=Q, 1=K, 2=V projection, 3=Wo->fp16.
// Proj: C[128 x 64] = X[128 x 64] * W[64 x 64]^T.
// ===========================================================================
__global__ __launch_bounds__(256) void proj_all(
    const float* __restrict__ q, const float* __restrict__ k,
    const float* __restrict__ v,
    const float* __restrict__ Wq, const float* __restrict__ Wk,
    const float* __restrict__ Wv,
    __half* __restrict__ Qp, __half* __restrict__ Kp, __half* __restrict__ Vp,
    const float* __restrict__ Wo, __half* __restrict__ Wt)
{
    const int t = threadIdx.x;
    if (blockIdx.y == 3) {
        int i = blockIdx.x * 256 + t;
        float4 w = reinterpret_cast<const float4*>(Wo)[i];
        uint2 u = make_uint2(pack2(w.x, w.y), pack2(w.z, w.w));
        *reinterpret_cast<uint2*>(reinterpret_cast<uint32_t*>(Wt) + i * 2) = u;
        return;
    }

    extern __shared__ uint32_t sm[];
    uint32_t* As = sm;            // [128][36] words
    uint32_t* Bs = sm + 128 * 36;

    const float* A = (blockIdx.y == 0) ? q : (blockIdx.y == 1) ? k : v;
    const float* B = (blockIdx.y == 0) ? Wq : (blockIdx.y == 1) ? Wk : Wv;
    __half* C = (blockIdx.y == 0) ? Qp : (blockIdx.y == 1) ? Kp : Vp;

    const int lane = t & 31, wid = t >> 5;
    const int wm = wid & 1, wn = wid >> 1;
    const int g = lane >> 2, tg = lane & 3;

    A += (long long)blockIdx.x * 128 * 64;

#pragma unroll
    for (int i = 0; i < 8; ++i) {
        int s = t + i * 256, r = s >> 4, c4 = (s & 15) << 2;
        float4 vv = *reinterpret_cast<const float4*>(A + (long long)r * 64 + c4);
        uint2 u = make_uint2(pack2(vv.x, vv.y), pack2(vv.z, vv.w));
        *reinterpret_cast<uint2*>(&As[r * 36 + (c4 >> 1)]) = u;
    }
#pragma unroll
    for (int i = 0; i < 4; ++i) {
        int s = t + i * 256, r = s >> 4, c4 = (s & 15) << 2;
        float4 vv = *reinterpret_cast<const float4*>(B + (long long)r * 64 + c4);
        uint2 u = make_uint2(pack2(vv.x, vv.y), pack2(vv.z, vv.w));
        *reinterpret_cast<uint2*>(&Bs[r * 36 + (c4 >> 1)]) = u;
    }
    __syncthreads();

    float acc[4][2][4];
#pragma unroll
    for (int i = 0; i < 4; ++i)
#pragma unroll
        for (int j = 0; j < 2; ++j)
#pragma unroll
            for (int e = 0; e < 4; ++e) acc[i][j][e] = 0.f;

#pragma unroll
    for (int ks = 0; ks < 4; ++ks) {
        int kb = ks * 8;
        uint32_t af[4][4];
#pragma unroll
        for (int mt = 0; mt < 4; ++mt) {
            int row = wm * 64 + mt * 16 + g;
            af[mt][0] = As[row * 36 + kb + tg];
            af[mt][1] = As[(row + 8) * 36 + kb + tg];
            af[mt][2] = As[row * 36 + kb + tg + 4];
            af[mt][3] = As[(row + 8) * 36 + kb + tg + 4];
        }
        uint32_t bf[2][2];
#pragma unroll
        for (int nt = 0; nt < 2; ++nt) {
            int col = wn * 16 + nt * 8 + g;
            bf[nt][0] = Bs[col * 36 + kb + tg];
            bf[nt][1] = Bs[col * 36 + kb + tg + 4];
        }
#pragma unroll
        for (int mt = 0; mt < 4; ++mt)
#pragma unroll
            for (int nt = 0; nt < 2; ++nt)
                mma16(acc[mt][nt], af[mt], bf[nt]);
    }

    uint32_t* Cw = reinterpret_cast<uint32_t*>(C) + (long long)blockIdx.x * 128 * 32;
#pragma unroll
    for (int mt = 0; mt < 4; ++mt) {
        int row = wm * 64 + mt * 16 + g;
#pragma unroll
        for (int nt = 0; nt < 2; ++nt) {
            int colw = (wn * 16 + nt * 8 + 2 * tg) >> 1;
            Cw[row * 32 + colw]       = pack2(acc[mt][nt][0], acc[mt][nt][1]);
            Cw[(row + 8) * 32 + colw] = pack2(acc[mt][nt][2], acc[mt][nt][3]);
        }
    }
}

// ===========================================================================
// Big GEMM: out[8192 x 1024] = AO * Wt^T, fp16 in, fp32 out. 128x128 tile,
// k-chunk 64, cp.async TRIPLE buffer (single syncthreads per chunk),
// ldmatrix frags, 2 CTAs/SM.
// smem words: As bufs 3*4608 at 0; Bs bufs 3*4608 at 13824. 110592 B.
// ===========================================================================
__global__ __launch_bounds__(256, 2) void gemm_big(
    const __half* __restrict__ A, const __half* __restrict__ B,
    float* __restrict__ C)
{
    extern __shared__ uint32_t sm[];
    const uint32_t sbase = smem_u32(sm);

    const int t = threadIdx.x, lane = t & 31, wid = t >> 5;
    const int wm = wid & 1, wn = wid >> 1;
    const int g = lane >> 2, tg = lane & 3;
    const int lA = laneA_off(lane), lB = laneB_off(lane);

    A += (long long)blockIdx.x * 128 * 1024;
    B += (long long)blockIdx.y * 128 * 1024;
    C += (long long)blockIdx.x * 128 * 1024 + (long long)blockIdx.y * 128;

    float acc[4][4][4];
#pragma unroll
    for (int i = 0; i < 4; ++i)
#pragma unroll
        for (int j = 0; j < 4; ++j)
#pragma unroll
            for (int e = 0; e < 4; ++e) acc[i][j][e] = 0.f;

    // prefetch chunk 0 into buf 0
#pragma unroll
    for (int i = 0; i < 4; ++i) {
        int s = t + i * 256, r = s >> 3, ch = s & 7;
        cp16(sbase + (r * 36 + ch * 4) * 4, A + (long long)r * 1024 + ch * 8);
        cp16(sbase + (13824 + r * 36 + ch * 4) * 4, B + (long long)r * 1024 + ch * 8);
    }
    CP_COMMIT();

    for (int ck = 0; ck < 16; ++ck) {
        if (ck < 15) {
            int kc = (ck + 1) * 64, b = (ck + 1) % 3;
#pragma unroll
            for (int i = 0; i < 4; ++i) {
                int s = t + i * 256, r = s >> 3, ch = s & 7;
                cp16(sbase + (b * 4608 + r * 36 + ch * 4) * 4,
                     A + (long long)r * 1024 + kc + ch * 8);
                cp16(sbase + (13824 + b * 4608 + r * 36 + ch * 4) * 4,
                     B + (long long)r * 1024 + kc + ch * 8);
            }
            CP_COMMIT();
            CP_WAIT(1);
        } else {
            CP_WAIT(0);
        }
        __syncthreads();   // single barrier per chunk (triple buffer)

        const int rb = ck % 3;
        const uint32_t Aad = sbase + (rb * 4608 + wm * 64 * 36 + lA) * 4;
        const uint32_t Bad = sbase + (13824 + rb * 4608 + wn * 32 * 36 + lB) * 4;
#pragma unroll
        for (int ks = 0; ks < 4; ++ks) {
            uint32_t af[4][4];
#pragma unroll
            for (int mt = 0; mt < 4; ++mt)
                ldsm4(af[mt], Aad + (mt * 16 * 36 + ks * 8) * 4);
            uint32_t bfp[2][4];
#pragma unroll
            for (int ntp = 0; ntp < 2; ++ntp)
                ldsm4(bfp[ntp], Bad + (ntp * 16 * 36 + ks * 8) * 4);
#pragma unroll
            for (int mt = 0; mt < 4; ++mt)
#pragma unroll
                for (int ntp = 0; ntp < 2; ++ntp) {
                    mma16(acc[mt][2 * ntp],     af[mt], &bfp[ntp][0]);
                    mma16(acc[mt][2 * ntp + 1], af[mt], &bfp[ntp][2]);
                }
        }
    }

#pragma unroll
    for (int mt = 0; mt < 4; ++mt) {
        int row = wm * 64 + mt * 16 + g;
#pragma unroll
        for (int nt = 0; nt < 4; ++nt) {
            int col = wn * 32 + nt * 8 + 2 * tg;
            *reinterpret_cast<float2*>(C + (long long)row * 1024 + col) =
                make_float2(acc[mt][nt][0], acc[mt][nt][1]);
            *reinterpret_cast<float2*>(C + (long long)(row + 8) * 1024 + col) =
                make_float2(acc[mt][nt][2], acc[mt][nt][3]);
        }
    }
}

// ===========================================================================
// Flash attention, fp16 mma m16n8k16, BK=64 TRIPLE-buffered (single sync per
// tile), 2 CTAs/SM. 8 warps x 16 q-rows. S/exp/PV fused per 16-col slice
// (ntp-outer) so independent S HMMAs hide the exp MUFU latency.
// smem words: Qs 0 (128*36=4608), K bufs 4608 + b*2304 (x3),
//             V bufs 11520 + b*2304 (x3). Total 18432 w = 73728 B.
// ===========================================================================
__global__ __launch_bounds__(256, 2) void attn_tc(
    const __half* __restrict__ Qp, const __half* __restrict__ Kp,
    const __half* __restrict__ Vp, __half* __restrict__ AO)
{
    extern __shared__ uint32_t sm[];
    const uint32_t sbase = smem_u32(sm);

    const int t = threadIdx.x, lane = t & 31, wid = t >> 5;
    const int g = lane >> 2, tg = lane & 3;
    const int lA = laneA_off(lane), lB = laneB_off(lane);
    const int qt = blockIdx.x, h = blockIdx.y, n = blockIdx.z;

    const long long base = ((long long)n << 20) + h * 64;          // halves
    const __half* Qb = Qp + base + (long long)(qt * 128) * 1024;

    // prefetch Q [128r x 32w] + K/V tile0 into buf0 (group 0)
#pragma unroll
    for (int i = 0; i < 4; ++i) {
        int s = t + i * 256, r = s >> 3, ch = s & 7;
        cp16(sbase + (r * 36 + ch * 4) * 4, Qb + (long long)r * 1024 + ch * 8);
    }
#pragma unroll
    for (int i = 0; i < 2; ++i) {
        int s = t + i * 256, r = s >> 3, ch = s & 7;
        cp16(sbase + (4608 + r * 36 + ch * 4) * 4, Kp + base + (long long)r * 1024 + ch * 8);
        cp16(sbase + (11520 + r * 36 + ch * 4) * 4, Vp + base + (long long)r * 1024 + ch * 8);
    }
    CP_COMMIT();

    float Of[8][4];
    float Osum[4] = {0.f, 0.f, 0.f, 0.f};
#pragma unroll
    for (int dtl = 0; dtl < 8; ++dtl)
#pragma unroll
        for (int e = 0; e < 4; ++e) Of[dtl][e] = 0.f;

    uint32_t Qa[4][4];                               // hoisted Q A-frags
    const float CS = 0.03125f * 1.44269504088896f;   // 1/sqrt(1024) * log2(e)
    const uint32_t ONES2[2] = {0x3C003C00u, 0x3C003C00u};

    for (int kt = 0; kt < 16; ++kt) {
        if (kt < 15) {
            int b = (kt + 1) % 3;
            const __half* Kb = Kp + base + (long long)((kt + 1) * 64) * 1024;
            const __half* Vb = Vp + base + (long long)((kt + 1) * 64) * 1024;
#pragma unroll
            for (int i = 0; i < 2; ++i) {
                int s = t + i * 256, r = s >> 3, ch = s & 7;
                cp16(sbase + (4608 + b * 2304 + r * 36 + ch * 4) * 4,
                     Kb + (long long)r * 1024 + ch * 8);
                cp16(sbase + (11520 + b * 2304 + r * 36 + ch * 4) * 4,
                     Vb + (long long)r * 1024 + ch * 8);
            }
            CP_COMMIT();
            CP_WAIT(1);
        } else {
            CP_WAIT(0);
        }
        __syncthreads();   // single barrier per tile (triple buffer)

        if (kt == 0) {
            uint32_t Qad = sbase + (wid * 16 * 36 + lA) * 4;
#pragma unroll
            for (int ds = 0; ds < 4; ++ds)
                ldsm4(Qa[ds], Qad + ds * 8 * 4);
        }

        const int rb = kt % 3;
        const uint32_t Kad = sbase + (4608 + rb * 2304 + lB) * 4;
        const uint32_t Vad = sbase + (11520 + rb * 2304 + lA) * 4;

        // ---- fused per 16-col slice: S -> exp -> lsum-mma -> PV ----
#pragma unroll
        for (int ntp = 0; ntp < 4; ++ntp) {
            float Sa[4] = {0.f, 0.f, 0.f, 0.f};
            float Sb[4] = {0.f, 0.f, 0.f, 0.f};
#pragma unroll
            for (int ds = 0; ds < 4; ++ds) {
                uint32_t bf[4];
                ldsm4(bf, Kad + (ntp * 16 * 36 + ds * 8) * 4);
                mma16(Sa, Qa[ds], &bf[0]);
                mma16(Sb, Qa[ds], &bf[2]);
            }
            uint32_t pa[4];
            pa[0] = h2exp2w(pack2(Sa[0] * CS, Sa[1] * CS));
            pa[1] = h2exp2w(pack2(Sa[2] * CS, Sa[3] * CS));
            pa[2] = h2exp2w(pack2(Sb[0] * CS, Sb[1] * CS));
            pa[3] = h2exp2w(pack2(Sb[2] * CS, Sb[3] * CS));
            mma16(Osum, pa, ONES2);   // row-sums of P
#pragma unroll
            for (int dp = 0; dp < 4; ++dp) {
                uint32_t bf[4];
                ldsm4t(bf, Vad + (ntp * 16 * 36 + dp * 8) * 4);
                mma16(Of[2 * dp],     pa, &bf[0]);
                mma16(Of[2 * dp + 1], pa, &bf[2]);
            }
        }
    }

    // ---- epilogue: normalize (Osum c0 = row g, c2 = row g+8), write ----
    float inv0 = 1.f / Osum[0], inv1 = 1.f / Osum[2];

    const int q0 = qt * 128 + wid * 16 + g;
    uint32_t* Ob0 = reinterpret_cast<uint32_t*>(AO)
                  + (((long long)n * 1024 + q0) * 1024 + h * 64) / 2;
    uint32_t* Ob1 = reinterpret_cast<uint32_t*>(AO)
                  + (((long long)n * 1024 + q0 + 8) * 1024 + h * 64) / 2;
#pragma unroll
    for (int dtl = 0; dtl < 8; ++dtl) {
        int dw = (dtl * 8 + 2 * tg) >> 1;
        Ob0[dw] = pack2(Of[dtl][0] * inv0, Of[dtl][1] * inv0);
        Ob1[dw] = pack2(Of[dtl][2] * inv1, Of[dtl][3] * inv1);
    }
}

// ===========================================================================
extern "C" void kernel_launch(void* const* d_in, const int* in_sizes, int n_in,
                              void* d_out, int out_size)
{
    (void)in_sizes; (void)n_in; (void)out_size;
    const float* key   = (const float*)d_in[0];
    const float* query = (const float*)d_in[1];
    const float* value = (const float*)d_in[2];
    /* d_in[3] = mask — faithfully ignored (reference no-op) */
    const float* Wq = (const float*)d_in[4];
    const float* Wk = (const float*)d_in[5];
    const float* Wv = (const float*)d_in[6];
    const float* Wo = (const float*)d_in[7];
    float* out = (float*)d_out;

    __half *Qp, *Kp, *Vp, *AO, *Wt;
    cudaGetSymbolAddress((void**)&Qp, g_Qp);
    cudaGetSymbolAddress((void**)&Kp, g_Kp);
    cudaGetSymbolAddress((void**)&Vp, g_Vp);
    cudaGetSymbolAddress((void**)&AO, g_AO);
    cudaGetSymbolAddress((void**)&Wt, g_Wt);

    const int smem_proj = (128 * 36 + 64 * 36) * 4;   // 27648
    const int smem_big  = 27648 * 4;                  // 110592
    const int smem_attn = 18432 * 4;                  // 73728
    cudaFuncSetAttribute(proj_all,
        cudaFuncAttributeMaxDynamicSharedMemorySize, smem_proj);
    cudaFuncSetAttribute(gemm_big,
        cudaFuncAttributeMaxDynamicSharedMemorySize, smem_big);
    cudaFuncSetAttribute(attn_tc,
        cudaFuncAttributeMaxDynamicSharedMemorySize, smem_attn);

    dim3 blk(256);

    // Fused projections (y=0..2) + Wo->fp16 (y=3)
    proj_all<<<dim3(1024, 4), blk, smem_proj>>>(
        query, key, value, Wq, Wk, Wv, Qp, Kp, Vp, Wo, Wt);

    // Attention: grid (q-tiles=8, heads=16, batch=8)
    attn_tc<<<dim3(8, NH, NB), blk, smem_attn>>>(Qp, Kp, Vp, AO);

    // Output projection: out = AO * Wt^T (fp16 in, fp32 out)
    gemm_big<<<dim3(64, 8), blk, smem_big>>>(AO, Wt, out);
}